// round 1
// baseline (speedup 1.0000x reference)
#include <cuda_runtime.h>
#include <cuda_bf16.h>
#include <cstdint>

// ---------------------------------------------------------------------------
// MCAT fused pipeline.
// Key simplification: softmax over a size-1 axis is identically 1, so
// fused = h_path @ wv_w + wv_b. q/k/x_cell paths are dead. ac_b is a uniform
// score shift -> softmax invariant -> dropped.
//
// Pipeline:
//   H = relu(X @ W1 + b1)            (50000,1024)@(1024,256)  bf16 MMA, split-wt
//   F = H @ Wv + bv                  (50000,256)@(256,256)
//   U = tanh(F @ aa + aa_b)
//   A[i] = sum_c sigmoid(F@ab+ab_b)[i,c] * U[i,c] * ac[c]   (gated score)
//   pooled = sum_i exp(A_i) F_i / sum_i exp(A_i)
//   out = relu(pooled@c1+b) @ c2 + b
// ---------------------------------------------------------------------------

#define MAXM 50048

__device__ __nv_bfloat16 g_H[(size_t)MAXM * 256];
__device__ __nv_bfloat16 g_F[(size_t)MAXM * 256];
__device__ __nv_bfloat16 g_U[(size_t)MAXM * 256];
__device__ float         g_A[MAXM];
__device__ float         g_P[260];   // [0..255] weighted sums, [256] weight denom

// ---------------- PTX helpers ----------------
__device__ __forceinline__ void ldsm_x4(uint32_t (&r)[4], const void* p) {
    uint32_t a = (uint32_t)__cvta_generic_to_shared(p);
    asm volatile("ldmatrix.sync.aligned.m8n8.x4.shared.b16 {%0,%1,%2,%3}, [%4];"
                 : "=r"(r[0]), "=r"(r[1]), "=r"(r[2]), "=r"(r[3]) : "r"(a));
}
__device__ __forceinline__ void ldsm_x2t(uint32_t (&r)[2], const void* p) {
    uint32_t a = (uint32_t)__cvta_generic_to_shared(p);
    asm volatile("ldmatrix.sync.aligned.m8n8.x2.trans.shared.b16 {%0,%1}, [%2];"
                 : "=r"(r[0]), "=r"(r[1]) : "r"(a));
}
__device__ __forceinline__ void mma_bf16(float (&c)[4], const uint32_t (&a)[4],
                                         const uint32_t (&b)[2]) {
    asm volatile(
        "mma.sync.aligned.m16n8k16.row.col.f32.bf16.bf16.f32 "
        "{%0,%1,%2,%3}, {%4,%5,%6,%7}, {%8,%9}, {%0,%1,%2,%3};"
        : "+f"(c[0]), "+f"(c[1]), "+f"(c[2]), "+f"(c[3])
        : "r"(a[0]), "r"(a[1]), "r"(a[2]), "r"(a[3]), "r"(b[0]), "r"(b[1]));
}

// ---------------- GEMM: (M,K) @ (K,256), BM=128 BN=128 BK=32, 8 warps -------
// MODE 0: relu  -> Out bf16
// MODE 1: none  -> Out bf16
// MODE 2: tanh  -> Out bf16
// MODE 3: gated score: sigmoid(v+bias)*U*ac, row-reduced -> atomicAdd Ascore
template <int K, int MODE, bool ABF16>
__global__ __launch_bounds__(256) void gemm_k(
    const float* __restrict__ Af, const __nv_bfloat16* __restrict__ Ab,
    const float* __restrict__ W, const float* __restrict__ bias,
    __nv_bfloat16* __restrict__ Out,
    const __nv_bfloat16* __restrict__ Uin, const float* __restrict__ acw,
    float* __restrict__ Ascore, int M) {

    __shared__ __nv_bfloat16 sA[128][40];    // padded: stride 80B = 5x16B
    __shared__ __nv_bfloat16 sBh[32][136];   // hi weights, stride 272B = 17x16B
    __shared__ __nv_bfloat16 sBl[32][136];   // lo residual weights

    const int tid  = threadIdx.x;
    const int lane = tid & 31;
    const int wid  = tid >> 5;
    const int wm   = wid & 3;   // warp m index 0..3 (rows wm*32..+31)
    const int wn   = wid >> 2;  // warp n index 0..1 (cols wn*64..+63)
    const int mBase = blockIdx.x * 128;
    const int nBase = blockIdx.y * 128;

    float acc[2][8][4];
#pragma unroll
    for (int mt = 0; mt < 2; mt++)
#pragma unroll
        for (int nt = 0; nt < 8; nt++)
#pragma unroll
            for (int i = 0; i < 4; i++) acc[mt][nt][i] = 0.f;

    // register staging for pipelined global loads
    float4 stA[4];
    uint4  stA16[2];
    float4 stB[4];

    auto loadA = [&](int k0) {
        if constexpr (ABF16) {
#pragma unroll
            for (int i = 0; i < 2; i++) {
                int r = (tid >> 2) + i * 64;
                int c = (tid & 3) * 8;
                int gr = mBase + r;
                if (gr < M)
                    stA16[i] = *reinterpret_cast<const uint4*>(&Ab[(size_t)gr * K + k0 + c]);
                else
                    stA16[i] = make_uint4(0, 0, 0, 0);
            }
        } else {
#pragma unroll
            for (int i = 0; i < 4; i++) {
                int r = (tid >> 3) + i * 32;
                int c = (tid & 7) * 4;
                int gr = mBase + r;
                if (gr < M)
                    stA[i] = *reinterpret_cast<const float4*>(&Af[(size_t)gr * K + k0 + c]);
                else
                    stA[i] = make_float4(0.f, 0.f, 0.f, 0.f);
            }
        }
    };
    auto loadB = [&](int k0) {
#pragma unroll
        for (int i = 0; i < 4; i++) {
            int r = (tid >> 5) + i * 8;
            int c = (tid & 31) * 4;
            stB[i] = *reinterpret_cast<const float4*>(&W[(size_t)(k0 + r) * 256 + nBase + c]);
        }
    };
    auto storeA = [&]() {
        if constexpr (ABF16) {
#pragma unroll
            for (int i = 0; i < 2; i++) {
                int r = (tid >> 2) + i * 64;
                int c = (tid & 3) * 8;
                *reinterpret_cast<uint4*>(&sA[r][c]) = stA16[i];
            }
        } else {
#pragma unroll
            for (int i = 0; i < 4; i++) {
                int r = (tid >> 3) + i * 32;
                int c = (tid & 7) * 4;
                __nv_bfloat162* p = reinterpret_cast<__nv_bfloat162*>(&sA[r][c]);
                p[0] = __floats2bfloat162_rn(stA[i].x, stA[i].y);
                p[1] = __floats2bfloat162_rn(stA[i].z, stA[i].w);
            }
        }
    };
    auto storeB = [&]() {
#pragma unroll
        for (int i = 0; i < 4; i++) {
            int r = (tid >> 5) + i * 8;
            int c = (tid & 31) * 4;
            float4 w = stB[i];
            __nv_bfloat16 hx = __float2bfloat16(w.x);
            __nv_bfloat16 hy = __float2bfloat16(w.y);
            __nv_bfloat16 hz = __float2bfloat16(w.z);
            __nv_bfloat16 hw = __float2bfloat16(w.w);
            __nv_bfloat162* ph = reinterpret_cast<__nv_bfloat162*>(&sBh[r][c]);
            ph[0] = __nv_bfloat162(hx, hy);
            ph[1] = __nv_bfloat162(hz, hw);
            __nv_bfloat162* pl = reinterpret_cast<__nv_bfloat162*>(&sBl[r][c]);
            pl[0] = __floats2bfloat162_rn(w.x - __bfloat162float(hx),
                                          w.y - __bfloat162float(hy));
            pl[1] = __floats2bfloat162_rn(w.z - __bfloat162float(hz),
                                          w.w - __bfloat162float(hw));
        }
    };
    auto compute = [&]() {
#pragma unroll
        for (int ks = 0; ks < 2; ks++) {
            uint32_t af[2][4];
#pragma unroll
            for (int mt = 0; mt < 2; mt++)
                ldsm_x4(af[mt], &sA[wm * 32 + mt * 16 + (lane & 15)][ks * 16 + (lane >> 4) * 8]);
#pragma unroll
            for (int nt = 0; nt < 8; nt++) {
                uint32_t bh[2], bl[2];
                const int br = ks * 16 + (lane & 15);
                const int bc = wn * 64 + nt * 8;
                ldsm_x2t(bh, &sBh[br][bc]);
                ldsm_x2t(bl, &sBl[br][bc]);
#pragma unroll
                for (int mt = 0; mt < 2; mt++) {
                    mma_bf16(acc[mt][nt], af[mt], bh);
                    mma_bf16(acc[mt][nt], af[mt], bl);
                }
            }
        }
    };

    constexpr int KT = K / 32;
    loadA(0);
    loadB(0);
#pragma unroll 1
    for (int kt = 0; kt < KT; kt++) {
        storeA();
        storeB();
        __syncthreads();
        if (kt + 1 < KT) { loadA((kt + 1) * 32); loadB((kt + 1) * 32); }
        compute();
        __syncthreads();
    }

    // -------- epilogue --------
#pragma unroll
    for (int mt = 0; mt < 2; mt++) {
#pragma unroll
        for (int r2 = 0; r2 < 2; r2++) {
            int rb = wm * 32 + mt * 16 + (lane >> 2) + r2 * 8;
            int gr = mBase + rb;
            float rsum = 0.f;
#pragma unroll
            for (int nt = 0; nt < 8; nt++) {
#pragma unroll
                for (int c2 = 0; c2 < 2; c2++) {
                    int cb = wn * 64 + nt * 8 + (lane & 3) * 2 + c2;
                    int gc = nBase + cb;
                    float v = acc[mt][nt][r2 * 2 + c2] + bias[gc];
                    if constexpr (MODE == 0) {
                        v = fmaxf(v, 0.f);
                        if (gr < M) Out[(size_t)gr * 256 + gc] = __float2bfloat16(v);
                    } else if constexpr (MODE == 1) {
                        if (gr < M) Out[(size_t)gr * 256 + gc] = __float2bfloat16(v);
                    } else if constexpr (MODE == 2) {
                        v = tanhf(v);
                        if (gr < M) Out[(size_t)gr * 256 + gc] = __float2bfloat16(v);
                    } else {
                        float g = 1.f / (1.f + expf(-v));
                        float u = (gr < M) ? __bfloat162float(Uin[(size_t)gr * 256 + gc]) : 0.f;
                        rsum += g * u * acw[gc];
                    }
                }
            }
            if constexpr (MODE == 3) {
                rsum += __shfl_xor_sync(0xffffffffu, rsum, 1);
                rsum += __shfl_xor_sync(0xffffffffu, rsum, 2);
                if ((lane & 3) == 0 && gr < M) atomicAdd(&Ascore[gr], rsum);
            }
        }
    }
}

// ---------------- zero scratch ----------------
__global__ void zero_k(float* A, float* P, int M) {
    int i = blockIdx.x * blockDim.x + threadIdx.x;
    if (i < M) A[i] = 0.f;
    if (i < 260) P[i] = 0.f;
}

// ---------------- exp-weighted pooling (no max-sub: |A| is tiny) -----------
__global__ __launch_bounds__(256) void pool_k(const __nv_bfloat16* __restrict__ F,
                                              const float* __restrict__ A,
                                              float* __restrict__ P, int M) {
    int d = threadIdx.x;  // 0..255
    float acc = 0.f, wsum = 0.f;
    for (int r = blockIdx.x; r < M; r += gridDim.x) {
        float w = expf(A[r]);
        acc += w * __bfloat162float(F[(size_t)r * 256 + d]);
        wsum += w;
    }
    atomicAdd(&P[d], acc);
    if (d == 0) atomicAdd(&P[256], wsum);
}

// ---------------- classifier ----------------
__global__ void cls_k(const float* __restrict__ P, const float* __restrict__ c1w,
                      const float* __restrict__ c1b, const float* __restrict__ c2w,
                      const float* __restrict__ c2b, float* __restrict__ out) {
    __shared__ float pd[256], h[128];
    int t = threadIdx.x;  // 128 threads
    float denom = P[256];
    pd[t]       = P[t] / denom;
    pd[t + 128] = P[t + 128] / denom;
    __syncthreads();
    float s = c1b[t];
#pragma unroll 8
    for (int d = 0; d < 256; d++) s += pd[d] * c1w[d * 128 + t];
    h[t] = fmaxf(s, 0.f);
    __syncthreads();
    if (t < 4) {
        float o = c2b[t];
#pragma unroll 8
        for (int j = 0; j < 128; j++) o += h[j] * c2w[j * 4 + t];
        out[t] = o;
    }
}

extern "C" void kernel_launch(void* const* d_in, const int* in_sizes, int n_in,
                              void* d_out, int out_size) {
    const float* x_path = (const float*)d_in[0];
    const float* wsi_w  = (const float*)d_in[2];
    const float* wsi_b  = (const float*)d_in[3];
    const float* wv_w   = (const float*)d_in[10];
    const float* wv_b   = (const float*)d_in[11];
    const float* aa_w   = (const float*)d_in[12];
    const float* aa_b   = (const float*)d_in[13];
    const float* ab_w   = (const float*)d_in[14];
    const float* ab_b   = (const float*)d_in[15];
    const float* ac_w   = (const float*)d_in[16];
    const float* c1_w   = (const float*)d_in[18];
    const float* c1_b   = (const float*)d_in[19];
    const float* c2_w   = (const float*)d_in[20];
    const float* c2_b   = (const float*)d_in[21];

    const int M = in_sizes[0] / 1024;
    const int MB = (M + 127) / 128;

    void* p;
    cudaGetSymbolAddress(&p, g_H); __nv_bfloat16* H = (__nv_bfloat16*)p;
    cudaGetSymbolAddress(&p, g_F); __nv_bfloat16* F = (__nv_bfloat16*)p;
    cudaGetSymbolAddress(&p, g_U); __nv_bfloat16* U = (__nv_bfloat16*)p;
    cudaGetSymbolAddress(&p, g_A); float* A = (float*)p;
    cudaGetSymbolAddress(&p, g_P); float* P = (float*)p;

    zero_k<<<(M + 255) / 256, 256>>>(A, P, M);
    // H = relu(X @ W1 + b1)
    gemm_k<1024, 0, false><<<dim3(MB, 2), 256>>>(x_path, nullptr, wsi_w, wsi_b, H,
                                                 nullptr, nullptr, nullptr, M);
    // F = H @ Wv + bv   (fused == v since softmax over size-1 axis == 1)
    gemm_k<256, 1, true><<<dim3(MB, 2), 256>>>(nullptr, H, wv_w, wv_b, F,
                                               nullptr, nullptr, nullptr, M);
    // U = tanh(F @ aa + aa_b)
    gemm_k<256, 2, true><<<dim3(MB, 2), 256>>>(nullptr, F, aa_w, aa_b, U,
                                               nullptr, nullptr, nullptr, M);
    // A = sum_c sigmoid(F@ab+ab_b) * U * ac
    gemm_k<256, 3, true><<<dim3(MB, 2), 256>>>(nullptr, F, ab_w, ab_b, nullptr,
                                               U, ac_w, A, M);
    // pooled numerator/denominator
    pool_k<<<256, 256>>>(F, A, P, M);
    // final classifier
    cls_k<<<1, 128>>>(P, c1_w, c1_b, c2_w, c2_b, (float*)d_out);
}

// round 2
// speedup vs baseline: 1.4985x; 1.4985x over previous
#include <cuda_runtime.h>
#include <cuda_bf16.h>
#include <cstdint>

// ---------------------------------------------------------------------------
// MCAT fused pipeline.
// Key simplification: softmax over a size-1 axis is identically 1, so
// fused = h_path @ wv_w + wv_b. q/k/x_cell paths are dead. ac_b is a uniform
// score shift -> softmax invariant -> dropped.
//
// Pipeline:
//   H = relu(X @ W1 + b1)            (50000,1024)@(1024,256)  bf16 MMA, split-wt
//   F = H @ Wv + bv                  (50000,256)@(256,256)
//   U = tanh(F @ aa + aa_b)
//   A[i] = sum_c sigmoid(F@ab+ab_b)[i,c] * U[i,c] * ac[c]   (gated score)
//   pooled = sum_i exp(A_i) F_i / sum_i exp(A_i)
//   out = relu(pooled@c1+b) @ c2 + b
// ---------------------------------------------------------------------------

#define MAXM 50048

__device__ __nv_bfloat16 g_H[(size_t)MAXM * 256];
__device__ __nv_bfloat16 g_F[(size_t)MAXM * 256];
__device__ __nv_bfloat16 g_U[(size_t)MAXM * 256];
__device__ float         g_A[MAXM];
__device__ float         g_P[260];   // [0..255] weighted sums, [256] weight denom

// ---------------- PTX helpers ----------------
__device__ __forceinline__ void ldsm_x4(uint32_t (&r)[4], const void* p) {
    uint32_t a = (uint32_t)__cvta_generic_to_shared(p);
    asm volatile("ldmatrix.sync.aligned.m8n8.x4.shared.b16 {%0,%1,%2,%3}, [%4];"
                 : "=r"(r[0]), "=r"(r[1]), "=r"(r[2]), "=r"(r[3]) : "r"(a));
}
__device__ __forceinline__ void ldsm_x2t(uint32_t (&r)[2], const void* p) {
    uint32_t a = (uint32_t)__cvta_generic_to_shared(p);
    asm volatile("ldmatrix.sync.aligned.m8n8.x2.trans.shared.b16 {%0,%1}, [%2];"
                 : "=r"(r[0]), "=r"(r[1]) : "r"(a));
}
__device__ __forceinline__ void mma_bf16(float (&c)[4], const uint32_t (&a)[4],
                                         const uint32_t (&b)[2]) {
    asm volatile(
        "mma.sync.aligned.m16n8k16.row.col.f32.bf16.bf16.f32 "
        "{%0,%1,%2,%3}, {%4,%5,%6,%7}, {%8,%9}, {%0,%1,%2,%3};"
        : "+f"(c[0]), "+f"(c[1]), "+f"(c[2]), "+f"(c[3])
        : "r"(a[0]), "r"(a[1]), "r"(a[2]), "r"(a[3]), "r"(b[0]), "r"(b[1]));
}

// ---------------- GEMM: (M,K) @ (K,256), BM=128 BN=128 BK=32, 8 warps -------
// MODE 0: relu  -> Out bf16
// MODE 1: none  -> Out bf16
// MODE 2: tanh  -> Out bf16
// MODE 3: gated score: sigmoid(v+bias)*U*ac, row-reduced -> atomicAdd Ascore
template <int K, int MODE, bool ABF16>
__global__ __launch_bounds__(256) void gemm_k(
    const float* __restrict__ Af, const __nv_bfloat16* __restrict__ Ab,
    const float* __restrict__ W, const float* __restrict__ bias,
    __nv_bfloat16* __restrict__ Out,
    const __nv_bfloat16* __restrict__ Uin, const float* __restrict__ acw,
    float* __restrict__ Ascore, int M) {

    __shared__ __nv_bfloat16 sA[128][40];    // padded: stride 80B = 5x16B
    __shared__ __nv_bfloat16 sBh[32][136];   // hi weights, stride 272B = 17x16B
    __shared__ __nv_bfloat16 sBl[32][136];   // lo residual weights

    const int tid  = threadIdx.x;
    const int lane = tid & 31;
    const int wid  = tid >> 5;
    const int wm   = wid & 3;   // warp m index 0..3 (rows wm*32..+31)
    const int wn   = wid >> 2;  // warp n index 0..1 (cols wn*64..+63)
    const int mBase = blockIdx.x * 128;
    const int nBase = blockIdx.y * 128;

    float acc[2][8][4];
#pragma unroll
    for (int mt = 0; mt < 2; mt++)
#pragma unroll
        for (int nt = 0; nt < 8; nt++)
#pragma unroll
            for (int i = 0; i < 4; i++) acc[mt][nt][i] = 0.f;

    // register staging for pipelined global loads
    float4 stA[4];
    uint4  stA16[2];
    float4 stB[4];

    auto loadA = [&](int k0) {
        if constexpr (ABF16) {
#pragma unroll
            for (int i = 0; i < 2; i++) {
                int r = (tid >> 2) + i * 64;
                int c = (tid & 3) * 8;
                int gr = mBase + r;
                if (gr < M)
                    stA16[i] = *reinterpret_cast<const uint4*>(&Ab[(size_t)gr * K + k0 + c]);
                else
                    stA16[i] = make_uint4(0, 0, 0, 0);
            }
        } else {
#pragma unroll
            for (int i = 0; i < 4; i++) {
                int r = (tid >> 3) + i * 32;
                int c = (tid & 7) * 4;
                int gr = mBase + r;
                if (gr < M)
                    stA[i] = *reinterpret_cast<const float4*>(&Af[(size_t)gr * K + k0 + c]);
                else
                    stA[i] = make_float4(0.f, 0.f, 0.f, 0.f);
            }
        }
    };
    auto loadB = [&](int k0) {
#pragma unroll
        for (int i = 0; i < 4; i++) {
            int r = (tid >> 5) + i * 8;
            int c = (tid & 31) * 4;
            stB[i] = *reinterpret_cast<const float4*>(&W[(size_t)(k0 + r) * 256 + nBase + c]);
        }
    };
    auto storeA = [&]() {
        if constexpr (ABF16) {
#pragma unroll
            for (int i = 0; i < 2; i++) {
                int r = (tid >> 2) + i * 64;
                int c = (tid & 3) * 8;
                *reinterpret_cast<uint4*>(&sA[r][c]) = stA16[i];
            }
        } else {
#pragma unroll
            for (int i = 0; i < 4; i++) {
                int r = (tid >> 3) + i * 32;
                int c = (tid & 7) * 4;
                __nv_bfloat162* p = reinterpret_cast<__nv_bfloat162*>(&sA[r][c]);
                p[0] = __floats2bfloat162_rn(stA[i].x, stA[i].y);
                p[1] = __floats2bfloat162_rn(stA[i].z, stA[i].w);
            }
        }
    };
    auto storeB = [&]() {
#pragma unroll
        for (int i = 0; i < 4; i++) {
            int r = (tid >> 5) + i * 8;
            int c = (tid & 31) * 4;
            float4 w = stB[i];
            __nv_bfloat16 hx = __float2bfloat16(w.x);
            __nv_bfloat16 hy = __float2bfloat16(w.y);
            __nv_bfloat16 hz = __float2bfloat16(w.z);
            __nv_bfloat16 hw = __float2bfloat16(w.w);
            __nv_bfloat162* ph = reinterpret_cast<__nv_bfloat162*>(&sBh[r][c]);
            ph[0] = __nv_bfloat162(hx, hy);
            ph[1] = __nv_bfloat162(hz, hw);
            __nv_bfloat162* pl = reinterpret_cast<__nv_bfloat162*>(&sBl[r][c]);
            pl[0] = __floats2bfloat162_rn(w.x - __bfloat162float(hx),
                                          w.y - __bfloat162float(hy));
            pl[1] = __floats2bfloat162_rn(w.z - __bfloat162float(hz),
                                          w.w - __bfloat162float(hw));
        }
    };
    auto compute = [&]() {
#pragma unroll
        for (int ks = 0; ks < 2; ks++) {
            uint32_t af[2][4];
#pragma unroll
            for (int mt = 0; mt < 2; mt++)
                ldsm_x4(af[mt], &sA[wm * 32 + mt * 16 + (lane & 15)][ks * 16 + (lane >> 4) * 8]);
#pragma unroll
            for (int nt = 0; nt < 8; nt++) {
                uint32_t bh[2], bl[2];
                const int br = ks * 16 + (lane & 15);
                const int bc = wn * 64 + nt * 8;
                ldsm_x2t(bh, &sBh[br][bc]);
                ldsm_x2t(bl, &sBl[br][bc]);
#pragma unroll
                for (int mt = 0; mt < 2; mt++) {
                    mma_bf16(acc[mt][nt], af[mt], bh);
                    mma_bf16(acc[mt][nt], af[mt], bl);
                }
            }
        }
    };

    constexpr int KT = K / 32;
    loadA(0);
    loadB(0);
#pragma unroll 1
    for (int kt = 0; kt < KT; kt++) {
        storeA();
        storeB();
        __syncthreads();
        if (kt + 1 < KT) { loadA((kt + 1) * 32); loadB((kt + 1) * 32); }
        compute();
        __syncthreads();
    }

    // -------- epilogue --------
#pragma unroll
    for (int mt = 0; mt < 2; mt++) {
#pragma unroll
        for (int r2 = 0; r2 < 2; r2++) {
            int rb = wm * 32 + mt * 16 + (lane >> 2) + r2 * 8;
            int gr = mBase + rb;
            float rsum = 0.f;
#pragma unroll
            for (int nt = 0; nt < 8; nt++) {
#pragma unroll
                for (int c2 = 0; c2 < 2; c2++) {
                    int cb = wn * 64 + nt * 8 + (lane & 3) * 2 + c2;
                    int gc = nBase + cb;
                    float v = acc[mt][nt][r2 * 2 + c2] + bias[gc];
                    if constexpr (MODE == 0) {
                        v = fmaxf(v, 0.f);
                        if (gr < M) Out[(size_t)gr * 256 + gc] = __float2bfloat16(v);
                    } else if constexpr (MODE == 1) {
                        if (gr < M) Out[(size_t)gr * 256 + gc] = __float2bfloat16(v);
                    } else if constexpr (MODE == 2) {
                        v = tanhf(v);
                        if (gr < M) Out[(size_t)gr * 256 + gc] = __float2bfloat16(v);
                    } else {
                        float g = 1.f / (1.f + expf(-v));
                        float u = (gr < M) ? __bfloat162float(Uin[(size_t)gr * 256 + gc]) : 0.f;
                        rsum += g * u * acw[gc];
                    }
                }
            }
            if constexpr (MODE == 3) {
                rsum += __shfl_xor_sync(0xffffffffu, rsum, 1);
                rsum += __shfl_xor_sync(0xffffffffu, rsum, 2);
                if ((lane & 3) == 0 && gr < M) atomicAdd(&Ascore[gr], rsum);
            }
        }
    }
}

// ---------------- zero scratch ----------------
__global__ void zero_k(float* A, float* P, int M) {
    int i = blockIdx.x * blockDim.x + threadIdx.x;
    if (i < M) A[i] = 0.f;
    if (i < 260) P[i] = 0.f;
}

// ---------------- exp-weighted pooling (no max-sub: |A| is tiny) -----------
__global__ __launch_bounds__(256) void pool_k(const __nv_bfloat16* __restrict__ F,
                                              const float* __restrict__ A,
                                              float* __restrict__ P, int M) {
    int d = threadIdx.x;  // 0..255
    float acc = 0.f, wsum = 0.f;
    for (int r = blockIdx.x; r < M; r += gridDim.x) {
        float w = expf(A[r]);
        acc += w * __bfloat162float(F[(size_t)r * 256 + d]);
        wsum += w;
    }
    atomicAdd(&P[d], acc);
    if (d == 0) atomicAdd(&P[256], wsum);
}

// ---------------- classifier ----------------
__global__ void cls_k(const float* __restrict__ P, const float* __restrict__ c1w,
                      const float* __restrict__ c1b, const float* __restrict__ c2w,
                      const float* __restrict__ c2b, float* __restrict__ out) {
    __shared__ float pd[256], h[128];
    int t = threadIdx.x;  // 128 threads
    float denom = P[256];
    pd[t]       = P[t] / denom;
    pd[t + 128] = P[t + 128] / denom;
    __syncthreads();
    float s = c1b[t];
#pragma unroll 8
    for (int d = 0; d < 256; d++) s += pd[d] * c1w[d * 128 + t];
    h[t] = fmaxf(s, 0.f);
    __syncthreads();
    if (t < 4) {
        float o = c2b[t];
#pragma unroll 8
        for (int j = 0; j < 128; j++) o += h[j] * c2w[j * 4 + t];
        out[t] = o;
    }
}

extern "C" void kernel_launch(void* const* d_in, const int* in_sizes, int n_in,
                              void* d_out, int out_size) {
    const float* x_path = (const float*)d_in[0];
    const float* wsi_w  = (const float*)d_in[2];
    const float* wsi_b  = (const float*)d_in[3];
    const float* wv_w   = (const float*)d_in[10];
    const float* wv_b   = (const float*)d_in[11];
    const float* aa_w   = (const float*)d_in[12];
    const float* aa_b   = (const float*)d_in[13];
    const float* ab_w   = (const float*)d_in[14];
    const float* ab_b   = (const float*)d_in[15];
    const float* ac_w   = (const float*)d_in[16];
    const float* c1_w   = (const float*)d_in[18];
    const float* c1_b   = (const float*)d_in[19];
    const float* c2_w   = (const float*)d_in[20];
    const float* c2_b   = (const float*)d_in[21];

    const int M = in_sizes[0] / 1024;
    const int MB = (M + 127) / 128;

    void* p;
    cudaGetSymbolAddress(&p, g_H); __nv_bfloat16* H = (__nv_bfloat16*)p;
    cudaGetSymbolAddress(&p, g_F); __nv_bfloat16* F = (__nv_bfloat16*)p;
    cudaGetSymbolAddress(&p, g_U); __nv_bfloat16* U = (__nv_bfloat16*)p;
    cudaGetSymbolAddress(&p, g_A); float* A = (float*)p;
    cudaGetSymbolAddress(&p, g_P); float* P = (float*)p;

    zero_k<<<(M + 255) / 256, 256>>>(A, P, M);
    // H = relu(X @ W1 + b1)
    gemm_k<1024, 0, false><<<dim3(MB, 2), 256>>>(x_path, nullptr, wsi_w, wsi_b, H,
                                                 nullptr, nullptr, nullptr, M);
    // F = H @ Wv + bv   (fused == v since softmax over size-1 axis == 1)
    gemm_k<256, 1, true><<<dim3(MB, 2), 256>>>(nullptr, H, wv_w, wv_b, F,
                                               nullptr, nullptr, nullptr, M);
    // U = tanh(F @ aa + aa_b)
    gemm_k<256, 2, true><<<dim3(MB, 2), 256>>>(nullptr, F, aa_w, aa_b, U,
                                               nullptr, nullptr, nullptr, M);
    // A = sum_c sigmoid(F@ab+ab_b) * U * ac
    gemm_k<256, 3, true><<<dim3(MB, 2), 256>>>(nullptr, F, ab_w, ab_b, nullptr,
                                               U, ac_w, A, M);
    // pooled numerator/denominator
    pool_k<<<256, 256>>>(F, A, P, M);
    // final classifier
    cls_k<<<1, 128>>>(P, c1_w, c1_b, c2_w, c2_b, (float*)d_out);
}

// round 9
// speedup vs baseline: 1.9091x; 1.2740x over previous
#include <cuda_runtime.h>
#include <cuda_bf16.h>
#include <cstdint>

// ============================================================================
// MCAT fused pipeline, mma.sync + cp.async.bulk edition (tcgen05 unavailable:
// harness compiles via compute_103 PTX; tcgen05 is sm_103a-only).
//
// Math: softmax over size-1 axis == 1 => fused = h_path@wv + bv; q/k/x_cell
// dead. ac_b softmax-invariant => dropped.
//
//   prepW: W -> bf16 hi/lo padded smem-image blocks [32][136] per (ktile,nhalf)
//   gemm1: H = relu(X@W1+b1), A: f32 LDG->cvt->STS double buffer,
//          B: 2-stage cp.async.bulk+mbarrier. H -> global in padded tile layout.
//   fused2 (1 CTA / 128 rows): bulk-load H tile; F = H@Wv+bv -> smem;
//          U = F@aa, G = F@ab (dual acc, one pass); score = sum sigmoid*tanh*ac;
//          pooled sums via atomics. F/U/G never touch HBM.
//   cls: classifier MLP.
// ============================================================================

#define MAXT 391

__device__ __align__(1024) __nv_bfloat16 g_W1h[64 * 4352];  // [kt*2+nh][32][136]
__device__ __align__(1024) __nv_bfloat16 g_W1l[64 * 4352];
__device__ __align__(1024) __nv_bfloat16 g_Wvh[16 * 4352];
__device__ __align__(1024) __nv_bfloat16 g_Wvl[16 * 4352];
__device__ __align__(1024) __nv_bfloat16 g_aah[16 * 4352];
__device__ __align__(1024) __nv_bfloat16 g_abh[16 * 4352];
__device__ __align__(1024) __nv_bfloat16 g_H[(size_t)MAXT * 8 * 5120]; // [mt][chunk][128][40]
__device__ float g_P[272];

// ---------------- PTX helpers ----------------
__device__ __forceinline__ uint32_t s2u(const void* p) {
    return (uint32_t)__cvta_generic_to_shared(p);
}
#define MBARRIER_INIT(mb, cnt) \
    asm volatile("mbarrier.init.shared.b64 [%0], %1;" :: "r"((uint32_t)(mb)), \
                 "r"((uint32_t)(cnt)) : "memory")
#define MBARRIER_EXPECT_TX(mb, tx) \
    asm volatile("mbarrier.arrive.expect_tx.shared.b64 _, [%0], %1;" \
                 :: "r"((uint32_t)(mb)), "r"((uint32_t)(tx)) : "memory")
#define MBARRIER_WAIT_PARITY(mb, par) do {                                     \
    uint32_t _mb = (uint32_t)(mb), _p = (uint32_t)(par), _done;                \
    asm volatile("{\n\t.reg .pred p;\n\t"                                      \
        "mbarrier.try_wait.parity.acquire.cta.shared::cta.b64 p, [%1], %2;\n\t"\
        "selp.b32 %0, 1, 0, p;\n\t}" : "=r"(_done) : "r"(_mb), "r"(_p) : "memory"); \
    if (!_done) {                                                              \
        asm volatile("{\n\t.reg .pred P1;\n\t"                                 \
            "WL_%=:\n\t"                                                       \
            "mbarrier.try_wait.parity.acquire.cta.shared::cta.b64 P1, [%0], %1, 0x989680;\n\t" \
            "@P1 bra.uni WD_%=;\n\t"                                           \
            "bra.uni WL_%=;\n\t"                                               \
            "WD_%=:\n\t}" :: "r"(_mb), "r"(_p) : "memory");                    \
    }                                                                          \
} while (0)

__device__ __forceinline__ void bulk_g2s(uint32_t dst, const void* src,
                                         uint32_t bytes, uint32_t mbar) {
    asm volatile(
        "cp.async.bulk.shared::cta.global.mbarrier::complete_tx::bytes "
        "[%0], [%1], %2, [%3];"
        :: "r"(dst), "l"(src), "r"(bytes), "r"(mbar) : "memory");
}
__device__ __forceinline__ void ldsm_x4(uint32_t (&r)[4], const void* p) {
    uint32_t a = s2u(p);
    asm volatile("ldmatrix.sync.aligned.m8n8.x4.shared.b16 {%0,%1,%2,%3}, [%4];"
                 : "=r"(r[0]), "=r"(r[1]), "=r"(r[2]), "=r"(r[3]) : "r"(a));
}
__device__ __forceinline__ void ldsm_x2t(uint32_t (&r)[2], const void* p) {
    uint32_t a = s2u(p);
    asm volatile("ldmatrix.sync.aligned.m8n8.x2.trans.shared.b16 {%0,%1}, [%2];"
                 : "=r"(r[0]), "=r"(r[1]) : "r"(a));
}
__device__ __forceinline__ void mma_bf16(float (&c)[4], const uint32_t (&a)[4],
                                         const uint32_t (&b)[2]) {
    asm volatile(
        "mma.sync.aligned.m16n8k16.row.col.f32.bf16.bf16.f32 "
        "{%0,%1,%2,%3}, {%4,%5,%6,%7}, {%8,%9}, {%0,%1,%2,%3};"
        : "+f"(c[0]), "+f"(c[1]), "+f"(c[2]), "+f"(c[3])
        : "r"(a[0]), "r"(a[1]), "r"(a[2]), "r"(a[3]), "r"(b[0]), "r"(b[1]));
}

// One 128x256(x32k) MMA step from padded smem images.
// sA: [128][40] bf16 (80B rows). sB0/sB1: [32][136] bf16 (272B rows).
// DUAL=false: both B blocks (hi/lo) accumulate into accA.
// DUAL=true:  sB0 -> accA, sB1 -> accB.
template <bool DUAL>
__device__ __forceinline__ void mma_tile(const char* sA, const char* sB0,
                                         const char* sB1, float (&accA)[2][8][4],
                                         float (&accB)[2][8][4], int wm, int wn,
                                         int lane) {
#pragma unroll
    for (int ks = 0; ks < 2; ks++) {
        uint32_t af[2][4];
#pragma unroll
        for (int m2 = 0; m2 < 2; m2++)
            ldsm_x4(af[m2], sA + (wm * 32 + m2 * 16 + (lane & 15)) * 80 +
                                (ks * 16 + (lane >> 4) * 8) * 2);
#pragma unroll
        for (int nt = 0; nt < 8; nt++) {
            uint32_t b0[2], b1[2];
            const int br = ks * 16 + (lane & 15);
            const int bc = wn * 64 + nt * 8;
            ldsm_x2t(b0, sB0 + br * 272 + bc * 2);
            ldsm_x2t(b1, sB1 + br * 272 + bc * 2);
#pragma unroll
            for (int m2 = 0; m2 < 2; m2++) {
                mma_bf16(accA[m2][nt], af[m2], b0);
                if (DUAL) mma_bf16(accB[m2][nt], af[m2], b1);
                else      mma_bf16(accA[m2][nt], af[m2], b1);
            }
        }
    }
}

// ---------------- prep: weights -> padded hi/lo smem images ----------------
__global__ void prepW_k(const float* __restrict__ W, __nv_bfloat16* __restrict__ Dh,
                        __nv_bfloat16* __restrict__ Dl, int K) {
    int i = blockIdx.x * blockDim.x + threadIdx.x;
    if (i >= K * 256) return;
    int k = i >> 8, n = i & 255;
    float v = W[i];
    int kt = k >> 5, ik = k & 31, nh = n >> 7, j = n & 127;
    size_t off = (size_t)(kt * 2 + nh) * 4352 + ik * 136 + j;
    __nv_bfloat16 h = __float2bfloat16(v);
    Dh[off] = h;
    if (Dl) Dl[off] = __float2bfloat16(v - __bfloat162float(h));
}

__global__ void zero_k(float* P) {
    if (threadIdx.x < 272) P[threadIdx.x] = 0.f;
}

// ---------------- GEMM1: H = relu(X @ W1 + b1) ----------------
#define G1_A    0          // 2 x 10240  (A bufs, [128][40] bf16)
#define G1_B    20480      // 2 x 17408  (B stages: hi 8704 + lo 8704)
#define G1_BAR  55296      // 2 mbarriers
#define G1_SMEM 55424

__global__ __launch_bounds__(256, 2) void gemm1_k(
    const float* __restrict__ X, const float* __restrict__ b1, int M) {
    extern __shared__ __align__(128) char smem[];
    uint32_t sb = s2u(smem);
    const int tid = threadIdx.x, lane = tid & 31, wid = tid >> 5;
    const int wm = wid & 3, wn = wid >> 2;
    const int mBase = blockIdx.x * 128, nh = blockIdx.y;

    if (tid == 0) {
        MBARRIER_INIT(sb + G1_BAR, 1);
        MBARRIER_INIT(sb + G1_BAR + 8, 1);
    }

    // A staging: thread covers row r = tid>>1, 16 cols at (tid&1)*16
    const int ar = tid >> 1, ac = (tid & 1) * 16;
    float4 st[4];
    auto loadA = [&](int kt) {
        const int gr = mBase + ar;
        if (gr < M) {
            const float* src = X + (size_t)gr * 1024 + kt * 32 + ac;
#pragma unroll
            for (int i = 0; i < 4; i++)
                st[i] = *reinterpret_cast<const float4*>(src + i * 4);
        } else {
#pragma unroll
            for (int i = 0; i < 4; i++) st[i] = make_float4(0.f, 0.f, 0.f, 0.f);
        }
    };
    auto storeA = [&](int kt) {
        char* dst = smem + G1_A + (kt & 1) * 10240 + ar * 80 + ac * 2;
#pragma unroll
        for (int i = 0; i < 4; i++) {
            __nv_bfloat162* p = reinterpret_cast<__nv_bfloat162*>(dst + i * 8);
            p[0] = __floats2bfloat162_rn(st[i].x, st[i].y);
            p[1] = __floats2bfloat162_rn(st[i].z, st[i].w);
        }
    };
    auto issueB = [&](int kt) {
        int s = kt & 1;
        uint32_t bar = sb + G1_BAR + s * 8;
        MBARRIER_EXPECT_TX(bar, 17408);
        size_t blk = (size_t)(kt * 2 + nh) * 4352;
        bulk_g2s(sb + G1_B + s * 17408, g_W1h + blk, 8704, bar);
        bulk_g2s(sb + G1_B + s * 17408 + 8704, g_W1l + blk, 8704, bar);
    };

    __syncthreads();  // barriers initialized before any expect_tx
    loadA(0);
    if (tid == 0) { issueB(0); issueB(1); }
    storeA(0);
    loadA(1);
    __syncthreads();  // A buf0 visible

    float acc[2][8][4];
    float accDummy[2][8][4];
#pragma unroll
    for (int m2 = 0; m2 < 2; m2++)
#pragma unroll
        for (int nt = 0; nt < 8; nt++)
#pragma unroll
            for (int i = 0; i < 4; i++) acc[m2][nt][i] = 0.f;

    for (int kt = 0; kt < 32; kt++) {
        const int s = kt & 1;
        MBARRIER_WAIT_PARITY(sb + G1_BAR + s * 8, (kt >> 1) & 1);
        const char* sA = smem + G1_A + s * 10240;
        const char* sB = smem + G1_B + s * 17408;
        mma_tile<false>(sA, sB, sB + 8704, acc, accDummy, wm, wn, lane);
        if (kt + 1 < 32) storeA(kt + 1);
        __syncthreads();  // A(kt+1) visible; B stage s drained by all warps
        if (kt + 2 < 32) {
            if (tid == 0) issueB(kt + 2);
            loadA(kt + 2);
        }
    }

    // epilogue: relu(acc + b1) -> g_H padded tile layout [mt][chunk][128][40]
    __nv_bfloat16* Ht = g_H + (size_t)blockIdx.x * 8 * 5120;
#pragma unroll
    for (int m2 = 0; m2 < 2; m2++) {
#pragma unroll
        for (int r2 = 0; r2 < 2; r2++) {
            const int rb = wm * 32 + m2 * 16 + (lane >> 2) + r2 * 8;
#pragma unroll
            for (int nt = 0; nt < 8; nt++) {
                const int cl = wn * 64 + nt * 8 + (lane & 3) * 2;
                const int gc = nh * 128 + cl;
                float v0 = fmaxf(acc[m2][nt][r2 * 2 + 0] + b1[gc], 0.f);
                float v1 = fmaxf(acc[m2][nt][r2 * 2 + 1] + b1[gc + 1], 0.f);
                *reinterpret_cast<__nv_bfloat162*>(
                    Ht + (gc >> 5) * 5120 + rb * 40 + (gc & 31)) =
                    __floats2bfloat162_rn(v0, v1);
            }
        }
    }
}

// ---------------- fused2: F, U, G, score, pooling ----------------
#define F2_H    0           // 81920: H tile image (8 chunks x [128][40])
#define F2_F    81920       // 81920: F image, same layout
#define F2_B    163840      // 2 stages x 17408
#define F2_BIAS 198656      // 1024 f32: bv, baa, bab, ac
#define F2_WROW 202752      // 128 f32
#define F2_BAR  203264      // barH + 2 stage bars
#define F2_SMEM 203392

__global__ __launch_bounds__(256, 1) void fused2_k(
    const float* __restrict__ bv, const float* __restrict__ baa,
    const float* __restrict__ bab, const float* __restrict__ acw, int M) {
    extern __shared__ __align__(128) char smem[];
    uint32_t sb = s2u(smem);
    const int tid = threadIdx.x, lane = tid & 31, wid = tid >> 5;
    const int wm = wid & 3, wn = wid >> 2;
    const int mt = blockIdx.x;

    if (tid == 0) {
        MBARRIER_INIT(sb + F2_BAR, 1);
        MBARRIER_INIT(sb + F2_BAR + 8, 1);
        MBARRIER_INIT(sb + F2_BAR + 16, 1);
    }
    __syncthreads();

    auto issueB = [&](int it) {
        int s = it & 1;
        uint32_t bar = sb + F2_BAR + 8 + s * 8;
        int np = (it >> 3) & 1, kt = it & 7;
        size_t blk = (size_t)(kt * 2 + np) * 4352;
        const __nv_bfloat16 *s0, *s1;
        if (it < 16) { s0 = g_Wvh + blk; s1 = g_Wvl + blk; }
        else         { s0 = g_aah + blk; s1 = g_abh + blk; }
        MBARRIER_EXPECT_TX(bar, 17408);
        bulk_g2s(sb + F2_B + s * 17408, s0, 8704, bar);
        bulk_g2s(sb + F2_B + s * 17408 + 8704, s1, 8704, bar);
    };

    if (tid == 0) {
        MBARRIER_EXPECT_TX(sb + F2_BAR, 81920);
        bulk_g2s(sb + F2_H, g_H + (size_t)mt * 8 * 5120, 81920, sb + F2_BAR);
        issueB(0);
        issueB(1);
    }
    float* sbias = (float*)(smem + F2_BIAS);
    float* wrow = (float*)(smem + F2_WROW);
    sbias[tid] = bv[tid];
    sbias[256 + tid] = baa[tid];
    sbias[512 + tid] = bab[tid];
    sbias[768 + tid] = acw[tid];
    if (tid < 128) wrow[tid] = 0.f;
    MBARRIER_WAIT_PARITY(sb + F2_BAR, 0);  // H tile ready
    __syncthreads();                       // biases/wrow visible

    int it = 0;
    // -------- GEMM2: F = H @ Wv + bv (hi/lo), two 128-col passes --------
    for (int np = 0; np < 2; np++) {
        float acc[2][8][4], accDummy[2][8][4];
#pragma unroll
        for (int m2 = 0; m2 < 2; m2++)
#pragma unroll
            for (int nt = 0; nt < 8; nt++)
#pragma unroll
                for (int i = 0; i < 4; i++) acc[m2][nt][i] = 0.f;
        for (int kt = 0; kt < 8; kt++, it++) {
            const int s = it & 1;
            MBARRIER_WAIT_PARITY(sb + F2_BAR + 8 + s * 8, (it >> 1) & 1);
            const char* sA = smem + F2_H + kt * 10240;
            const char* sB = smem + F2_B + s * 17408;
            mma_tile<false>(sA, sB, sB + 8704, acc, accDummy, wm, wn, lane);
            __syncthreads();
            if (tid == 0 && it + 2 < 32) issueB(it + 2);
        }
        // epilogue: F = acc + bv -> smem F image  ([chunk][128][40], 5120 elem/chunk)
        __nv_bfloat16* Fi = (__nv_bfloat16*)(smem + F2_F);
#pragma unroll
        for (int m2 = 0; m2 < 2; m2++)
#pragma unroll
            for (int r2 = 0; r2 < 2; r2++) {
                const int rb = wm * 32 + m2 * 16 + (lane >> 2) + r2 * 8;
#pragma unroll
                for (int nt = 0; nt < 8; nt++) {
                    const int cl = wn * 64 + nt * 8 + (lane & 3) * 2;
                    const int gc = np * 128 + cl;
                    float v0 = acc[m2][nt][r2 * 2 + 0] + sbias[gc];
                    float v1 = acc[m2][nt][r2 * 2 + 1] + sbias[gc + 1];
                    *reinterpret_cast<__nv_bfloat162*>(
                        Fi + (gc >> 5) * 5120 + rb * 40 + (gc & 31)) =
                        __floats2bfloat162_rn(v0, v1);
                }
            }
    }
    __syncthreads();  // F image complete

    // -------- GEMM3/4: U = F@aa, G = F@ab (dual acc), + gated score --------
    for (int np = 0; np < 2; np++) {
        float aU[2][8][4], aG[2][8][4];
#pragma unroll
        for (int m2 = 0; m2 < 2; m2++)
#pragma unroll
            for (int nt = 0; nt < 8; nt++)
#pragma unroll
                for (int i = 0; i < 4; i++) { aU[m2][nt][i] = 0.f; aG[m2][nt][i] = 0.f; }
        for (int kt = 0; kt < 8; kt++, it++) {
            const int s = it & 1;
            MBARRIER_WAIT_PARITY(sb + F2_BAR + 8 + s * 8, (it >> 1) & 1);
            const char* sA = smem + F2_F + kt * 10240;
            const char* sB = smem + F2_B + s * 17408;
            mma_tile<true>(sA, sB, sB + 8704, aU, aG, wm, wn, lane);
            __syncthreads();
            if (tid == 0 && it + 2 < 32) issueB(it + 2);
        }
        // partial gated score per owned cell, reduce across quad, atomics to wrow
#pragma unroll
        for (int m2 = 0; m2 < 2; m2++)
#pragma unroll
            for (int r2 = 0; r2 < 2; r2++) {
                const int rb = wm * 32 + m2 * 16 + (lane >> 2) + r2 * 8;
                float rs = 0.f;
#pragma unroll
                for (int nt = 0; nt < 8; nt++)
#pragma unroll
                    for (int c2 = 0; c2 < 2; c2++) {
                        const int gc = np * 128 + wn * 64 + nt * 8 + (lane & 3) * 2 + c2;
                        float u = tanhf(aU[m2][nt][r2 * 2 + c2] + sbias[256 + gc]);
                        float g = 1.f / (1.f + expf(-(aG[m2][nt][r2 * 2 + c2] + sbias[512 + gc])));
                        rs += g * u * sbias[768 + gc];
                    }
                rs += __shfl_xor_sync(0xffffffffu, rs, 1);
                rs += __shfl_xor_sync(0xffffffffu, rs, 2);
                if ((lane & 3) == 0) atomicAdd(&wrow[rb], rs);
            }
    }
    __syncthreads();

    // exp weights (|score| tiny -> no max subtraction), mask padded rows
    if (tid < 128) {
        const int gr = mt * 128 + tid;
        wrow[tid] = (gr < M) ? expf(wrow[tid]) : 0.f;
    }
    __syncthreads();

    // pooling: P[c] += sum_r w_r * F[r,c];  P[256] += sum_r w_r
    {
        const int c = tid;
        const __nv_bfloat16* col =
            (const __nv_bfloat16*)(smem + F2_F) + (c >> 5) * 5120 + (c & 31);
        float a = 0.f;
#pragma unroll 4
        for (int r = 0; r < 128; r++) a += wrow[r] * __bfloat162float(col[r * 40]);
        atomicAdd(&g_P[c], a);
    }
    if (wid == 0) {
        float s = wrow[lane] + wrow[lane + 32] + wrow[lane + 64] + wrow[lane + 96];
#pragma unroll
        for (int o = 16; o; o >>= 1) s += __shfl_xor_sync(0xffffffffu, s, o);
        if (lane == 0) atomicAdd(&g_P[256], s);
    }
}

// ---------------- classifier ----------------
__global__ void cls_k(const float* __restrict__ P, const float* __restrict__ c1w,
                      const float* __restrict__ c1b, const float* __restrict__ c2w,
                      const float* __restrict__ c2b, float* __restrict__ out) {
    __shared__ float pd[256], h[128];
    int t = threadIdx.x;  // 128 threads
    float denom = P[256];
    pd[t] = P[t] / denom;
    pd[t + 128] = P[t + 128] / denom;
    __syncthreads();
    float s = c1b[t];
#pragma unroll 8
    for (int d = 0; d < 256; d++) s += pd[d] * c1w[d * 128 + t];
    h[t] = fmaxf(s, 0.f);
    __syncthreads();
    if (t < 4) {
        float o = c2b[t];
#pragma unroll 8
        for (int j = 0; j < 128; j++) o += h[j] * c2w[j * 4 + t];
        out[t] = o;
    }
}

extern "C" void kernel_launch(void* const* d_in, const int* in_sizes, int n_in,
                              void* d_out, int out_size) {
    const float* x_path = (const float*)d_in[0];
    const float* wsi_w = (const float*)d_in[2];
    const float* wsi_b = (const float*)d_in[3];
    const float* wv_w = (const float*)d_in[10];
    const float* wv_b = (const float*)d_in[11];
    const float* aa_w = (const float*)d_in[12];
    const float* aa_b = (const float*)d_in[13];
    const float* ab_w = (const float*)d_in[14];
    const float* ab_b = (const float*)d_in[15];
    const float* ac_w = (const float*)d_in[16];
    const float* c1_w = (const float*)d_in[18];
    const float* c1_b = (const float*)d_in[19];
    const float* c2_w = (const float*)d_in[20];
    const float* c2_b = (const float*)d_in[21];

    const int M = in_sizes[0] / 1024;
    const int NT = (M + 127) / 128;

    void* p;
    __nv_bfloat16 *W1h, *W1l, *Wvh, *Wvl, *aah, *abh;
    float* P;
    cudaGetSymbolAddress(&p, g_W1h); W1h = (__nv_bfloat16*)p;
    cudaGetSymbolAddress(&p, g_W1l); W1l = (__nv_bfloat16*)p;
    cudaGetSymbolAddress(&p, g_Wvh); Wvh = (__nv_bfloat16*)p;
    cudaGetSymbolAddress(&p, g_Wvl); Wvl = (__nv_bfloat16*)p;
    cudaGetSymbolAddress(&p, g_aah); aah = (__nv_bfloat16*)p;
    cudaGetSymbolAddress(&p, g_abh); abh = (__nv_bfloat16*)p;
    cudaGetSymbolAddress(&p, g_P); P = (float*)p;

    cudaFuncSetAttribute(gemm1_k, cudaFuncAttributeMaxDynamicSharedMemorySize,
                         G1_SMEM);
    cudaFuncSetAttribute(fused2_k, cudaFuncAttributeMaxDynamicSharedMemorySize,
                         F2_SMEM);

    zero_k<<<1, 288>>>(P);
    prepW_k<<<1024, 256>>>(wsi_w, W1h, W1l, 1024);
    prepW_k<<<256, 256>>>(wv_w, Wvh, Wvl, 256);
    prepW_k<<<256, 256>>>(aa_w, aah, nullptr, 256);
    prepW_k<<<256, 256>>>(ab_w, abh, nullptr, 256);
    gemm1_k<<<dim3(NT, 2), 256, G1_SMEM>>>(x_path, wsi_b, M);
    fused2_k<<<NT, 256, F2_SMEM>>>(wv_b, aa_b, ab_b, ac_w, M);
    cls_k<<<1, 128>>>(P, c1_w, c1_b, c2_w, c2_b, (float*)d_out);
}

// round 10
// speedup vs baseline: 2.4045x; 1.2595x over previous
#include <cuda_runtime.h>
#include <cuda_bf16.h>
#include <cstdint>

// ============================================================================
// MCAT fused pipeline, mma.sync + cp.async.bulk edition (tcgen05 unavailable:
// harness compiles via compute_103 PTX; tcgen05 is sm_103a-only).
//
// Math: softmax over size-1 axis == 1 => fused = h_path@wv + bv; q/k/x_cell
// dead. ac_b softmax-invariant => dropped.
//
//   prepW: W -> bf16 (hi[/lo]) padded smem-image blocks [32][136] per (kt,nh)
//   gemm1: H = relu(X@W1+b1), W1 single bf16 (quantization noise ~zero-mean
//          across pooled instances). A: f32 LDG->cvt->STS double buffer,
//          B: 2-stage cp.async.bulk+mbarrier. Grid (2,NT) so both nh-halves of
//          one X tile are adjacent -> X read once from DRAM, 2nd hits L2.
//   fused2 (1 CTA / 128 rows): bulk-load H tile; F = H@Wv+bv (hi/lo) -> smem;
//          U = F@aa, G = F@ab (dual acc, one pass); score = sum sigmoid*tanh*ac;
//          pooled sums via atomics. F/U/G never touch HBM.
//   cls: classifier MLP.
// ============================================================================

#define MAXT 391

__device__ __align__(1024) __nv_bfloat16 g_W1h[64 * 4352];  // [kt*2+nh][32][136]
__device__ __align__(1024) __nv_bfloat16 g_Wvh[16 * 4352];
__device__ __align__(1024) __nv_bfloat16 g_Wvl[16 * 4352];
__device__ __align__(1024) __nv_bfloat16 g_aah[16 * 4352];
__device__ __align__(1024) __nv_bfloat16 g_abh[16 * 4352];
__device__ __align__(1024) __nv_bfloat16 g_H[(size_t)MAXT * 8 * 5120]; // [mt][chunk][128][40]
__device__ float g_P[272];

// ---------------- PTX helpers ----------------
__device__ __forceinline__ uint32_t s2u(const void* p) {
    return (uint32_t)__cvta_generic_to_shared(p);
}
#define MBARRIER_INIT(mb, cnt) \
    asm volatile("mbarrier.init.shared.b64 [%0], %1;" :: "r"((uint32_t)(mb)), \
                 "r"((uint32_t)(cnt)) : "memory")
#define MBARRIER_EXPECT_TX(mb, tx) \
    asm volatile("mbarrier.arrive.expect_tx.shared.b64 _, [%0], %1;" \
                 :: "r"((uint32_t)(mb)), "r"((uint32_t)(tx)) : "memory")
#define MBARRIER_WAIT_PARITY(mb, par) do {                                     \
    uint32_t _mb = (uint32_t)(mb), _p = (uint32_t)(par), _done;                \
    asm volatile("{\n\t.reg .pred p;\n\t"                                      \
        "mbarrier.try_wait.parity.acquire.cta.shared::cta.b64 p, [%1], %2;\n\t"\
        "selp.b32 %0, 1, 0, p;\n\t}" : "=r"(_done) : "r"(_mb), "r"(_p) : "memory"); \
    if (!_done) {                                                              \
        asm volatile("{\n\t.reg .pred P1;\n\t"                                 \
            "WL_%=:\n\t"                                                       \
            "mbarrier.try_wait.parity.acquire.cta.shared::cta.b64 P1, [%0], %1, 0x989680;\n\t" \
            "@P1 bra.uni WD_%=;\n\t"                                           \
            "bra.uni WL_%=;\n\t"                                               \
            "WD_%=:\n\t}" :: "r"(_mb), "r"(_p) : "memory");                    \
    }                                                                          \
} while (0)

__device__ __forceinline__ void bulk_g2s(uint32_t dst, const void* src,
                                         uint32_t bytes, uint32_t mbar) {
    asm volatile(
        "cp.async.bulk.shared::cta.global.mbarrier::complete_tx::bytes "
        "[%0], [%1], %2, [%3];"
        :: "r"(dst), "l"(src), "r"(bytes), "r"(mbar) : "memory");
}
__device__ __forceinline__ void ldsm_x4(uint32_t (&r)[4], const void* p) {
    uint32_t a = s2u(p);
    asm volatile("ldmatrix.sync.aligned.m8n8.x4.shared.b16 {%0,%1,%2,%3}, [%4];"
                 : "=r"(r[0]), "=r"(r[1]), "=r"(r[2]), "=r"(r[3]) : "r"(a));
}
__device__ __forceinline__ void ldsm_x2t(uint32_t (&r)[2], const void* p) {
    uint32_t a = s2u(p);
    asm volatile("ldmatrix.sync.aligned.m8n8.x2.trans.shared.b16 {%0,%1}, [%2];"
                 : "=r"(r[0]), "=r"(r[1]) : "r"(a));
}
__device__ __forceinline__ void mma_bf16(float (&c)[4], const uint32_t (&a)[4],
                                         const uint32_t (&b)[2]) {
    asm volatile(
        "mma.sync.aligned.m16n8k16.row.col.f32.bf16.bf16.f32 "
        "{%0,%1,%2,%3}, {%4,%5,%6,%7}, {%8,%9}, {%0,%1,%2,%3};"
        : "+f"(c[0]), "+f"(c[1]), "+f"(c[2]), "+f"(c[3])
        : "r"(a[0]), "r"(a[1]), "r"(a[2]), "r"(a[3]), "r"(b[0]), "r"(b[1]));
}

// One 128x256(x32k) MMA step from padded smem images.
// sA: [128][40] bf16 (80B rows). sB0/sB1: [32][136] bf16 (272B rows).
// MODE 0: sB0 and sB1 both accumulate into accA (hi/lo sum).
// MODE 1: sB0 -> accA, sB1 -> accB (dual outputs).
// MODE 2: sB0 -> accA only (sB1 unused).
template <int MODE>
__device__ __forceinline__ void mma_tile(const char* sA, const char* sB0,
                                         const char* sB1, float (&accA)[2][8][4],
                                         float (&accB)[2][8][4], int wm, int wn,
                                         int lane) {
#pragma unroll
    for (int ks = 0; ks < 2; ks++) {
        uint32_t af[2][4];
#pragma unroll
        for (int m2 = 0; m2 < 2; m2++)
            ldsm_x4(af[m2], sA + (wm * 32 + m2 * 16 + (lane & 15)) * 80 +
                                (ks * 16 + (lane >> 4) * 8) * 2);
#pragma unroll
        for (int nt = 0; nt < 8; nt++) {
            uint32_t b0[2], b1[2];
            const int br = ks * 16 + (lane & 15);
            const int bc = wn * 64 + nt * 8;
            ldsm_x2t(b0, sB0 + br * 272 + bc * 2);
            if (MODE != 2) ldsm_x2t(b1, sB1 + br * 272 + bc * 2);
#pragma unroll
            for (int m2 = 0; m2 < 2; m2++) {
                mma_bf16(accA[m2][nt], af[m2], b0);
                if (MODE == 0)      mma_bf16(accA[m2][nt], af[m2], b1);
                else if (MODE == 1) mma_bf16(accB[m2][nt], af[m2], b1);
            }
        }
    }
}

// ---------------- prep: weights -> padded hi/lo smem images ----------------
__global__ void prepW_k(const float* __restrict__ W, __nv_bfloat16* __restrict__ Dh,
                        __nv_bfloat16* __restrict__ Dl, int K) {
    int i = blockIdx.x * blockDim.x + threadIdx.x;
    if (i >= K * 256) return;
    int k = i >> 8, n = i & 255;
    float v = W[i];
    int kt = k >> 5, ik = k & 31, nh = n >> 7, j = n & 127;
    size_t off = (size_t)(kt * 2 + nh) * 4352 + ik * 136 + j;
    __nv_bfloat16 h = __float2bfloat16(v);
    Dh[off] = h;
    if (Dl) Dl[off] = __float2bfloat16(v - __bfloat162float(h));
}

__global__ void zero_k(float* P) {
    if (threadIdx.x < 272) P[threadIdx.x] = 0.f;
}

// ---------------- GEMM1: H = relu(X @ W1 + b1), single-bf16 W1 ----------------
#define G1_A    0          // 2 x 10240  (A bufs, [128][40] bf16)
#define G1_B    20480      // 2 x 8704   (B stages, hi only)
#define G1_BAR  37888      // 2 mbarriers
#define G1_SMEM 38016

__global__ __launch_bounds__(256, 2) void gemm1_k(
    const float* __restrict__ X, const float* __restrict__ b1, int M) {
    extern __shared__ __align__(128) char smem[];
    uint32_t sb = s2u(smem);
    const int tid = threadIdx.x, lane = tid & 31, wid = tid >> 5;
    const int wm = wid & 3, wn = wid >> 2;
    const int nh = blockIdx.x, mt = blockIdx.y;   // nh fastest: X tile L2 reuse
    const int mBase = mt * 128;

    if (tid == 0) {
        MBARRIER_INIT(sb + G1_BAR, 1);
        MBARRIER_INIT(sb + G1_BAR + 8, 1);
    }

    // A staging: thread covers row r = tid>>1, 16 cols at (tid&1)*16
    const int ar = tid >> 1, ac = (tid & 1) * 16;
    float4 st[4];
    auto loadA = [&](int kt) {
        const int gr = mBase + ar;
        if (gr < M) {
            const float* src = X + (size_t)gr * 1024 + kt * 32 + ac;
#pragma unroll
            for (int i = 0; i < 4; i++)
                st[i] = *reinterpret_cast<const float4*>(src + i * 4);
        } else {
#pragma unroll
            for (int i = 0; i < 4; i++) st[i] = make_float4(0.f, 0.f, 0.f, 0.f);
        }
    };
    auto storeA = [&](int kt) {
        char* dst = smem + G1_A + (kt & 1) * 10240 + ar * 80 + ac * 2;
#pragma unroll
        for (int i = 0; i < 4; i++) {
            __nv_bfloat162* p = reinterpret_cast<__nv_bfloat162*>(dst + i * 8);
            p[0] = __floats2bfloat162_rn(st[i].x, st[i].y);
            p[1] = __floats2bfloat162_rn(st[i].z, st[i].w);
        }
    };
    auto issueB = [&](int kt) {
        int s = kt & 1;
        uint32_t bar = sb + G1_BAR + s * 8;
        MBARRIER_EXPECT_TX(bar, 8704);
        bulk_g2s(sb + G1_B + s * 8704, g_W1h + (size_t)(kt * 2 + nh) * 4352,
                 8704, bar);
    };

    __syncthreads();  // barriers initialized before any expect_tx
    loadA(0);
    if (tid == 0) { issueB(0); issueB(1); }
    storeA(0);
    loadA(1);
    __syncthreads();  // A buf0 visible

    float acc[2][8][4];
    float accDummy[2][8][4];
#pragma unroll
    for (int m2 = 0; m2 < 2; m2++)
#pragma unroll
        for (int nt = 0; nt < 8; nt++)
#pragma unroll
            for (int i = 0; i < 4; i++) acc[m2][nt][i] = 0.f;

    for (int kt = 0; kt < 32; kt++) {
        const int s = kt & 1;
        MBARRIER_WAIT_PARITY(sb + G1_BAR + s * 8, (kt >> 1) & 1);
        const char* sA = smem + G1_A + s * 10240;
        const char* sB = smem + G1_B + s * 8704;
        mma_tile<2>(sA, sB, nullptr, acc, accDummy, wm, wn, lane);
        if (kt + 1 < 32) storeA(kt + 1);
        __syncthreads();  // A(kt+1) visible; B stage s drained by all warps
        if (kt + 2 < 32) {
            if (tid == 0) issueB(kt + 2);
            loadA(kt + 2);
        }
    }

    // epilogue: relu(acc + b1) -> g_H padded tile layout [mt][chunk][128][40]
    __nv_bfloat16* Ht = g_H + (size_t)mt * 8 * 5120;
#pragma unroll
    for (int m2 = 0; m2 < 2; m2++) {
#pragma unroll
        for (int r2 = 0; r2 < 2; r2++) {
            const int rb = wm * 32 + m2 * 16 + (lane >> 2) + r2 * 8;
#pragma unroll
            for (int nt = 0; nt < 8; nt++) {
                const int cl = wn * 64 + nt * 8 + (lane & 3) * 2;
                const int gc = nh * 128 + cl;
                float v0 = fmaxf(acc[m2][nt][r2 * 2 + 0] + b1[gc], 0.f);
                float v1 = fmaxf(acc[m2][nt][r2 * 2 + 1] + b1[gc + 1], 0.f);
                *reinterpret_cast<__nv_bfloat162*>(
                    Ht + (gc >> 5) * 5120 + rb * 40 + (gc & 31)) =
                    __floats2bfloat162_rn(v0, v1);
            }
        }
    }
}

// ---------------- fused2: F, U, G, score, pooling ----------------
#define F2_H    0           // 81920: H tile image (8 chunks x [128][40])
#define F2_F    81920       // 81920: F image, same layout
#define F2_B    163840      // 2 stages x 17408
#define F2_BIAS 198656      // 1024 f32: bv, baa, bab, ac
#define F2_WROW 202752      // 128 f32
#define F2_BAR  203264      // barH + 2 stage bars
#define F2_SMEM 203392

__global__ __launch_bounds__(256, 1) void fused2_k(
    const float* __restrict__ bv, const float* __restrict__ baa,
    const float* __restrict__ bab, const float* __restrict__ acw, int M) {
    extern __shared__ __align__(128) char smem[];
    uint32_t sb = s2u(smem);
    const int tid = threadIdx.x, lane = tid & 31, wid = tid >> 5;
    const int wm = wid & 3, wn = wid >> 2;
    const int mt = blockIdx.x;

    if (tid == 0) {
        MBARRIER_INIT(sb + F2_BAR, 1);
        MBARRIER_INIT(sb + F2_BAR + 8, 1);
        MBARRIER_INIT(sb + F2_BAR + 16, 1);
    }
    __syncthreads();

    auto issueB = [&](int it) {
        int s = it & 1;
        uint32_t bar = sb + F2_BAR + 8 + s * 8;
        int np = (it >> 3) & 1, kt = it & 7;
        size_t blk = (size_t)(kt * 2 + np) * 4352;
        const __nv_bfloat16 *s0, *s1;
        if (it < 16) { s0 = g_Wvh + blk; s1 = g_Wvl + blk; }
        else         { s0 = g_aah + blk; s1 = g_abh + blk; }
        MBARRIER_EXPECT_TX(bar, 17408);
        bulk_g2s(sb + F2_B + s * 17408, s0, 8704, bar);
        bulk_g2s(sb + F2_B + s * 17408 + 8704, s1, 8704, bar);
    };

    if (tid == 0) {
        MBARRIER_EXPECT_TX(sb + F2_BAR, 81920);
        bulk_g2s(sb + F2_H, g_H + (size_t)mt * 8 * 5120, 81920, sb + F2_BAR);
        issueB(0);
        issueB(1);
    }
    float* sbias = (float*)(smem + F2_BIAS);
    float* wrow = (float*)(smem + F2_WROW);
    sbias[tid] = bv[tid];
    sbias[256 + tid] = baa[tid];
    sbias[512 + tid] = bab[tid];
    sbias[768 + tid] = acw[tid];
    if (tid < 128) wrow[tid] = 0.f;
    MBARRIER_WAIT_PARITY(sb + F2_BAR, 0);  // H tile ready
    __syncthreads();                       // biases/wrow visible

    int it = 0;
    // -------- GEMM2: F = H @ Wv + bv (hi/lo), two 128-col passes --------
    for (int np = 0; np < 2; np++) {
        float acc[2][8][4], accDummy[2][8][4];
#pragma unroll
        for (int m2 = 0; m2 < 2; m2++)
#pragma unroll
            for (int nt = 0; nt < 8; nt++)
#pragma unroll
                for (int i = 0; i < 4; i++) acc[m2][nt][i] = 0.f;
        for (int kt = 0; kt < 8; kt++, it++) {
            const int s = it & 1;
            MBARRIER_WAIT_PARITY(sb + F2_BAR + 8 + s * 8, (it >> 1) & 1);
            const char* sA = smem + F2_H + kt * 10240;
            const char* sB = smem + F2_B + s * 17408;
            mma_tile<0>(sA, sB, sB + 8704, acc, accDummy, wm, wn, lane);
            __syncthreads();
            if (tid == 0 && it + 2 < 32) issueB(it + 2);
        }
        // epilogue: F = acc + bv -> smem F image  ([chunk][128][40], 5120 elem/chunk)
        __nv_bfloat16* Fi = (__nv_bfloat16*)(smem + F2_F);
#pragma unroll
        for (int m2 = 0; m2 < 2; m2++)
#pragma unroll
            for (int r2 = 0; r2 < 2; r2++) {
                const int rb = wm * 32 + m2 * 16 + (lane >> 2) + r2 * 8;
#pragma unroll
                for (int nt = 0; nt < 8; nt++) {
                    const int cl = wn * 64 + nt * 8 + (lane & 3) * 2;
                    const int gc = np * 128 + cl;
                    float v0 = acc[m2][nt][r2 * 2 + 0] + sbias[gc];
                    float v1 = acc[m2][nt][r2 * 2 + 1] + sbias[gc + 1];
                    *reinterpret_cast<__nv_bfloat162*>(
                        Fi + (gc >> 5) * 5120 + rb * 40 + (gc & 31)) =
                        __floats2bfloat162_rn(v0, v1);
                }
            }
    }
    __syncthreads();  // F image complete

    // -------- GEMM3/4: U = F@aa, G = F@ab (dual acc), + gated score --------
    for (int np = 0; np < 2; np++) {
        float aU[2][8][4], aG[2][8][4];
#pragma unroll
        for (int m2 = 0; m2 < 2; m2++)
#pragma unroll
            for (int nt = 0; nt < 8; nt++)
#pragma unroll
                for (int i = 0; i < 4; i++) { aU[m2][nt][i] = 0.f; aG[m2][nt][i] = 0.f; }
        for (int kt = 0; kt < 8; kt++, it++) {
            const int s = it & 1;
            MBARRIER_WAIT_PARITY(sb + F2_BAR + 8 + s * 8, (it >> 1) & 1);
            const char* sA = smem + F2_F + kt * 10240;
            const char* sB = smem + F2_B + s * 17408;
            mma_tile<1>(sA, sB, sB + 8704, aU, aG, wm, wn, lane);
            __syncthreads();
            if (tid == 0 && it + 2 < 32) issueB(it + 2);
        }
        // partial gated score per owned cell, reduce across quad, atomics to wrow
#pragma unroll
        for (int m2 = 0; m2 < 2; m2++)
#pragma unroll
            for (int r2 = 0; r2 < 2; r2++) {
                const int rb = wm * 32 + m2 * 16 + (lane >> 2) + r2 * 8;
                float rs = 0.f;
#pragma unroll
                for (int nt = 0; nt < 8; nt++)
#pragma unroll
                    for (int c2 = 0; c2 < 2; c2++) {
                        const int gc = np * 128 + wn * 64 + nt * 8 + (lane & 3) * 2 + c2;
                        float u = tanhf(aU[m2][nt][r2 * 2 + c2] + sbias[256 + gc]);
                        float g = 1.f / (1.f + expf(-(aG[m2][nt][r2 * 2 + c2] + sbias[512 + gc])));
                        rs += g * u * sbias[768 + gc];
                    }
                rs += __shfl_xor_sync(0xffffffffu, rs, 1);
                rs += __shfl_xor_sync(0xffffffffu, rs, 2);
                if ((lane & 3) == 0) atomicAdd(&wrow[rb], rs);
            }
    }
    __syncthreads();

    // exp weights (|score| tiny -> no max subtraction), mask padded rows
    if (tid < 128) {
        const int gr = mt * 128 + tid;
        wrow[tid] = (gr < M) ? expf(wrow[tid]) : 0.f;
    }
    __syncthreads();

    // pooling: P[c] += sum_r w_r * F[r,c];  P[256] += sum_r w_r
    {
        const int c = tid;
        const __nv_bfloat16* col =
            (const __nv_bfloat16*)(smem + F2_F) + (c >> 5) * 5120 + (c & 31);
        float a = 0.f;
#pragma unroll 4
        for (int r = 0; r < 128; r++) a += wrow[r] * __bfloat162float(col[r * 40]);
        atomicAdd(&g_P[c], a);
    }
    if (wid == 0) {
        float s = wrow[lane] + wrow[lane + 32] + wrow[lane + 64] + wrow[lane + 96];
#pragma unroll
        for (int o = 16; o; o >>= 1) s += __shfl_xor_sync(0xffffffffu, s, o);
        if (lane == 0) atomicAdd(&g_P[256], s);
    }
}

// ---------------- classifier ----------------
__global__ void cls_k(const float* __restrict__ P, const float* __restrict__ c1w,
                      const float* __restrict__ c1b, const float* __restrict__ c2w,
                      const float* __restrict__ c2b, float* __restrict__ out) {
    __shared__ float pd[256], h[128];
    int t = threadIdx.x;  // 128 threads
    float denom = P[256];
    pd[t] = P[t] / denom;
    pd[t + 128] = P[t + 128] / denom;
    __syncthreads();
    float s = c1b[t];
#pragma unroll 8
    for (int d = 0; d < 256; d++) s += pd[d] * c1w[d * 128 + t];
    h[t] = fmaxf(s, 0.f);
    __syncthreads();
    if (t < 4) {
        float o = c2b[t];
#pragma unroll 8
        for (int j = 0; j < 128; j++) o += h[j] * c2w[j * 4 + t];
        out[t] = o;
    }
}

extern "C" void kernel_launch(void* const* d_in, const int* in_sizes, int n_in,
                              void* d_out, int out_size) {
    const float* x_path = (const float*)d_in[0];
    const float* wsi_w = (const float*)d_in[2];
    const float* wsi_b = (const float*)d_in[3];
    const float* wv_w = (const float*)d_in[10];
    const float* wv_b = (const float*)d_in[11];
    const float* aa_w = (const float*)d_in[12];
    const float* aa_b = (const float*)d_in[13];
    const float* ab_w = (const float*)d_in[14];
    const float* ab_b = (const float*)d_in[15];
    const float* ac_w = (const float*)d_in[16];
    const float* c1_w = (const float*)d_in[18];
    const float* c1_b = (const float*)d_in[19];
    const float* c2_w = (const float*)d_in[20];
    const float* c2_b = (const float*)d_in[21];

    const int M = in_sizes[0] / 1024;
    const int NT = (M + 127) / 128;

    void* p;
    __nv_bfloat16 *W1h, *Wvh, *Wvl, *aah, *abh;
    float* P;
    cudaGetSymbolAddress(&p, g_W1h); W1h = (__nv_bfloat16*)p;
    cudaGetSymbolAddress(&p, g_Wvh); Wvh = (__nv_bfloat16*)p;
    cudaGetSymbolAddress(&p, g_Wvl); Wvl = (__nv_bfloat16*)p;
    cudaGetSymbolAddress(&p, g_aah); aah = (__nv_bfloat16*)p;
    cudaGetSymbolAddress(&p, g_abh); abh = (__nv_bfloat16*)p;
    cudaGetSymbolAddress(&p, g_P); P = (float*)p;

    cudaFuncSetAttribute(gemm1_k, cudaFuncAttributeMaxDynamicSharedMemorySize,
                         G1_SMEM);
    cudaFuncSetAttribute(fused2_k, cudaFuncAttributeMaxDynamicSharedMemorySize,
                         F2_SMEM);

    zero_k<<<1, 288>>>(P);
    prepW_k<<<1024, 256>>>(wsi_w, W1h, nullptr, 1024);
    prepW_k<<<256, 256>>>(wv_w, Wvh, Wvl, 256);
    prepW_k<<<256, 256>>>(aa_w, aah, nullptr, 256);
    prepW_k<<<256, 256>>>(ab_w, abh, nullptr, 256);
    gemm1_k<<<dim3(2, NT), 256, G1_SMEM>>>(x_path, wsi_b, M);
    fused2_k<<<NT, 256, F2_SMEM>>>(wv_b, aa_b, ab_b, ac_w, M);
    cls_k<<<1, 128>>>(P, c1_w, c1_b, c2_w, c2_b, (float*)d_out);
}

// round 16
// speedup vs baseline: 2.4750x; 1.0293x over previous
#include <cuda_runtime.h>
#include <cuda_bf16.h>
#include <cstdint>

// ============================================================================
// MCAT fused pipeline, mma.sync + cp.async.bulk edition (tcgen05 unavailable:
// harness compiles via compute_103 PTX; tcgen05 is sm_103a-only).
//
// Math: softmax over size-1 axis == 1 => fused = h_path@wv + bv; q/k/x_cell
// dead. ac_b softmax-invariant => dropped.
// Precision: W1 single bf16 (error decorrelates through relu+3 GEMMs+nonlin
// before pooling). Wv hi/lo: pooled output is linear in F, so dWv is
// systematic (R12 lesson). aa/ab single bf16 (perturb attention weights only).
// R14 lesson: g_P[256] (pool denominator) MUST be zeroed every call — device
// globals are only zero-initialized at module load, and graph replays
// accumulate otherwise.
//
//   prep_all: all weights -> bf16 padded smem-image blocks [32][136]; zero P.
//   gemm1: H = relu(X@W1+b1). A: f32 LDG->cvt->STS double buffer,
//          B: 2-stage cp.async.bulk+mbarrier. Grid (2,NT): X tile L2 reuse.
//   fused2 (1 CTA / 128 rows): bulk-load H tile; F = H@Wv+bv (hi/lo) -> smem;
//          U = F@aa, G = F@ab (dual acc); score = sum sigmoid*tanh*ac;
//          pooled sums via atomics. F/U/G never touch HBM.
//   cls: classifier MLP.
// Warp layout 2m x 4n (64 rows x 32 cols per warp): halves redundant
// B-ldmatrix traffic vs 4m x 2n for dual/hi-lo tiles.
// ============================================================================

#define MAXT 391

__device__ __align__(1024) __nv_bfloat16 g_W1h[64 * 4352];  // [kt*2+nh][32][136]
__device__ __align__(1024) __nv_bfloat16 g_Wvh[16 * 4352];
__device__ __align__(1024) __nv_bfloat16 g_Wvl[16 * 4352];
__device__ __align__(1024) __nv_bfloat16 g_aah[16 * 4352];
__device__ __align__(1024) __nv_bfloat16 g_abh[16 * 4352];
__device__ __align__(1024) __nv_bfloat16 g_H[(size_t)MAXT * 8 * 5120]; // [mt][chunk][128][40]
__device__ float g_P[272];

// ---------------- PTX helpers ----------------
__device__ __forceinline__ uint32_t s2u(const void* p) {
    return (uint32_t)__cvta_generic_to_shared(p);
}
#define MBARRIER_INIT(mb, cnt) \
    asm volatile("mbarrier.init.shared.b64 [%0], %1;" :: "r"((uint32_t)(mb)), \
                 "r"((uint32_t)(cnt)) : "memory")
#define MBARRIER_EXPECT_TX(mb, tx) \
    asm volatile("mbarrier.arrive.expect_tx.shared.b64 _, [%0], %1;" \
                 :: "r"((uint32_t)(mb)), "r"((uint32_t)(tx)) : "memory")
#define MBARRIER_WAIT_PARITY(mb, par) do {                                     \
    uint32_t _mb = (uint32_t)(mb), _p = (uint32_t)(par), _done;                \
    asm volatile("{\n\t.reg .pred p;\n\t"                                      \
        "mbarrier.try_wait.parity.acquire.cta.shared::cta.b64 p, [%1], %2;\n\t"\
        "selp.b32 %0, 1, 0, p;\n\t}" : "=r"(_done) : "r"(_mb), "r"(_p) : "memory"); \
    if (!_done) {                                                              \
        asm volatile("{\n\t.reg .pred P1;\n\t"                                 \
            "WL_%=:\n\t"                                                       \
            "mbarrier.try_wait.parity.acquire.cta.shared::cta.b64 P1, [%0], %1, 0x989680;\n\t" \
            "@P1 bra.uni WD_%=;\n\t"                                           \
            "bra.uni WL_%=;\n\t"                                               \
            "WD_%=:\n\t}" :: "r"(_mb), "r"(_p) : "memory");                    \
    }                                                                          \
} while (0)

__device__ __forceinline__ void bulk_g2s(uint32_t dst, const void* src,
                                         uint32_t bytes, uint32_t mbar) {
    asm volatile(
        "cp.async.bulk.shared::cta.global.mbarrier::complete_tx::bytes "
        "[%0], [%1], %2, [%3];"
        :: "r"(dst), "l"(src), "r"(bytes), "r"(mbar) : "memory");
}
__device__ __forceinline__ void ldsm_x4(uint32_t (&r)[4], const void* p) {
    uint32_t a = s2u(p);
    asm volatile("ldmatrix.sync.aligned.m8n8.x4.shared.b16 {%0,%1,%2,%3}, [%4];"
                 : "=r"(r[0]), "=r"(r[1]), "=r"(r[2]), "=r"(r[3]) : "r"(a));
}
__device__ __forceinline__ void ldsm_x2t(uint32_t (&r)[2], const void* p) {
    uint32_t a = s2u(p);
    asm volatile("ldmatrix.sync.aligned.m8n8.x2.trans.shared.b16 {%0,%1}, [%2];"
                 : "=r"(r[0]), "=r"(r[1]) : "r"(a));
}
__device__ __forceinline__ void mma_bf16(float (&c)[4], const uint32_t (&a)[4],
                                         const uint32_t (&b)[2]) {
    asm volatile(
        "mma.sync.aligned.m16n8k16.row.col.f32.bf16.bf16.f32 "
        "{%0,%1,%2,%3}, {%4,%5,%6,%7}, {%8,%9}, {%0,%1,%2,%3};"
        : "+f"(c[0]), "+f"(c[1]), "+f"(c[2]), "+f"(c[3])
        : "r"(a[0]), "r"(a[1]), "r"(a[2]), "r"(a[3]), "r"(b[0]), "r"(b[1]));
}

// One 128x256(x32k) MMA step from padded smem images, 2m x 4n warp layout.
// sA: [128][40] bf16 (80B rows). sB0/sB1: [32][136] bf16 (272B rows).
// wm = wid&1 (rows wm*64..+63 as 4 m16 tiles), wn = wid>>1 (cols wn*32..+31
// as 4 n8 tiles).
// MODE 0: sB0 and sB1 both accumulate into accA (hi/lo sum).
// MODE 1: sB0 -> accA, sB1 -> accB (dual outputs).
// MODE 2: sB0 -> accA only (sB1 unused).
template <int MODE>
__device__ __forceinline__ void mma_tile(const char* sA, const char* sB0,
                                         const char* sB1, float (&accA)[4][4][4],
                                         float (&accB)[4][4][4], int wm, int wn,
                                         int lane) {
#pragma unroll
    for (int ks = 0; ks < 2; ks++) {
        uint32_t af[4][4];
#pragma unroll
        for (int m2 = 0; m2 < 4; m2++)
            ldsm_x4(af[m2], sA + (wm * 64 + m2 * 16 + (lane & 15)) * 80 +
                                (ks * 16 + (lane >> 4) * 8) * 2);
#pragma unroll
        for (int nt = 0; nt < 4; nt++) {
            uint32_t b0[2], b1[2];
            const int br = ks * 16 + (lane & 15);
            const int bc = wn * 32 + nt * 8;
            ldsm_x2t(b0, sB0 + br * 272 + bc * 2);
            if (MODE != 2) ldsm_x2t(b1, sB1 + br * 272 + bc * 2);
#pragma unroll
            for (int m2 = 0; m2 < 4; m2++) {
                mma_bf16(accA[m2][nt], af[m2], b0);
                if (MODE == 0)      mma_bf16(accA[m2][nt], af[m2], b1);
                else if (MODE == 1) mma_bf16(accB[m2][nt], af[m2], b1);
            }
        }
    }
}

// ---------------- prep: all weights -> padded bf16 images; zero P -----------
__device__ __forceinline__ void prep_one(const float* W, __nv_bfloat16* Dh,
                                         __nv_bfloat16* Dl, int i) {
    int k = i >> 8, n = i & 255;
    int kt = k >> 5, ik = k & 31, nh = n >> 7, j = n & 127;
    size_t off = (size_t)(kt * 2 + nh) * 4352 + ik * 136 + j;
    float v = W[i];
    __nv_bfloat16 h = __float2bfloat16(v);
    Dh[off] = h;
    if (Dl) Dl[off] = __float2bfloat16(v - __bfloat162float(h));
}

__global__ void prep_all(const float* __restrict__ w1, const float* __restrict__ wv,
                         const float* __restrict__ aa, const float* __restrict__ ab) {
    int b = blockIdx.x, tid = threadIdx.x;
    if (b < 1024) {
        prep_one(w1, g_W1h, nullptr, b * 256 + tid);
    } else if (b < 1280) {
        prep_one(wv, g_Wvh, g_Wvl, (b - 1024) * 256 + tid);
    } else if (b < 1536) {
        prep_one(aa, g_aah, nullptr, (b - 1280) * 256 + tid);
    } else if (b < 1792) {
        prep_one(ab, g_abh, nullptr, (b - 1536) * 256 + tid);
    } else {
        // zero ALL 272 floats incl. g_P[256] denominator (R14 lesson:
        // blockDim is 256, so tid<272 alone misses 256..271).
        g_P[tid] = 0.f;
        if (tid < 16) g_P[256 + tid] = 0.f;
    }
}

// ---------------- GEMM1: H = relu(X @ W1 + b1), single-bf16 W1 ----------------
#define G1_A    0          // 2 x 10240  (A bufs, [128][40] bf16)
#define G1_B    20480      // 2 x 8704   (B stages, hi only)
#define G1_BAR  37888      // 2 mbarriers
#define G1_SMEM 38016

__global__ __launch_bounds__(256, 2) void gemm1_k(
    const float* __restrict__ X, const float* __restrict__ b1, int M) {
    extern __shared__ __align__(128) char smem[];
    uint32_t sb = s2u(smem);
    const int tid = threadIdx.x, lane = tid & 31, wid = tid >> 5;
    const int wm = wid & 1, wn = wid >> 1;
    const int nh = blockIdx.x, mt = blockIdx.y;   // nh fastest: X tile L2 reuse
    const int mBase = mt * 128;

    if (tid == 0) {
        MBARRIER_INIT(sb + G1_BAR, 1);
        MBARRIER_INIT(sb + G1_BAR + 8, 1);
    }

    // A staging: thread covers row r = tid>>1, 16 cols at (tid&1)*16
    const int ar = tid >> 1, ac = (tid & 1) * 16;
    float4 st[4];
    auto loadA = [&](int kt) {
        const int gr = mBase + ar;
        if (gr < M) {
            const float* src = X + (size_t)gr * 1024 + kt * 32 + ac;
#pragma unroll
            for (int i = 0; i < 4; i++)
                st[i] = *reinterpret_cast<const float4*>(src + i * 4);
        } else {
#pragma unroll
            for (int i = 0; i < 4; i++) st[i] = make_float4(0.f, 0.f, 0.f, 0.f);
        }
    };
    auto storeA = [&](int kt) {
        char* dst = smem + G1_A + (kt & 1) * 10240 + ar * 80 + ac * 2;
#pragma unroll
        for (int i = 0; i < 4; i++) {
            __nv_bfloat162* p = reinterpret_cast<__nv_bfloat162*>(dst + i * 8);
            p[0] = __floats2bfloat162_rn(st[i].x, st[i].y);
            p[1] = __floats2bfloat162_rn(st[i].z, st[i].w);
        }
    };
    auto issueB = [&](int kt) {
        int s = kt & 1;
        uint32_t bar = sb + G1_BAR + s * 8;
        MBARRIER_EXPECT_TX(bar, 8704);
        bulk_g2s(sb + G1_B + s * 8704, g_W1h + (size_t)(kt * 2 + nh) * 4352,
                 8704, bar);
    };

    __syncthreads();  // barriers initialized before any expect_tx
    loadA(0);
    if (tid == 0) { issueB(0); issueB(1); }
    storeA(0);
    loadA(1);
    __syncthreads();  // A buf0 visible

    float acc[4][4][4];
    float accDummy[4][4][4];
#pragma unroll
    for (int m2 = 0; m2 < 4; m2++)
#pragma unroll
        for (int nt = 0; nt < 4; nt++)
#pragma unroll
            for (int i = 0; i < 4; i++) acc[m2][nt][i] = 0.f;

    for (int kt = 0; kt < 32; kt++) {
        const int s = kt & 1;
        MBARRIER_WAIT_PARITY(sb + G1_BAR + s * 8, (kt >> 1) & 1);
        const char* sA = smem + G1_A + s * 10240;
        const char* sB = smem + G1_B + s * 8704;
        mma_tile<2>(sA, sB, nullptr, acc, accDummy, wm, wn, lane);
        if (kt + 1 < 32) storeA(kt + 1);
        __syncthreads();  // A(kt+1) visible; B stage s drained by all warps
        if (kt + 2 < 32) {
            if (tid == 0) issueB(kt + 2);
            loadA(kt + 2);
        }
    }

    // epilogue: relu(acc + b1) -> g_H padded tile layout [mt][chunk][128][40]
    __nv_bfloat16* Ht = g_H + (size_t)mt * 8 * 5120;
#pragma unroll
    for (int m2 = 0; m2 < 4; m2++) {
#pragma unroll
        for (int r2 = 0; r2 < 2; r2++) {
            const int rb = wm * 64 + m2 * 16 + (lane >> 2) + r2 * 8;
#pragma unroll
            for (int nt = 0; nt < 4; nt++) {
                const int cl = wn * 32 + nt * 8 + (lane & 3) * 2;
                const int gc = nh * 128 + cl;
                float v0 = fmaxf(acc[m2][nt][r2 * 2 + 0] + b1[gc], 0.f);
                float v1 = fmaxf(acc[m2][nt][r2 * 2 + 1] + b1[gc + 1], 0.f);
                *reinterpret_cast<__nv_bfloat162*>(
                    Ht + (gc >> 5) * 5120 + rb * 40 + (gc & 31)) =
                    __floats2bfloat162_rn(v0, v1);
            }
        }
    }
}

// ---------------- fused2: F, U, G, score, pooling ----------------
#define F2_H    0           // 81920: H tile image (8 chunks x [128][40])
#define F2_F    81920       // 81920: F image, same layout
#define F2_B    163840      // 2 stages x 17408
#define F2_BIAS 198656      // 1024 f32: bv, baa, bab, ac
#define F2_WROW 202752      // 128 f32
#define F2_BAR  203264      // barH + 2 stage bars
#define F2_SMEM 203392

__global__ __launch_bounds__(256, 1) void fused2_k(
    const float* __restrict__ bv, const float* __restrict__ baa,
    const float* __restrict__ bab, const float* __restrict__ acw, int M) {
    extern __shared__ __align__(128) char smem[];
    uint32_t sb = s2u(smem);
    const int tid = threadIdx.x, lane = tid & 31, wid = tid >> 5;
    const int wm = wid & 1, wn = wid >> 1;
    const int mt = blockIdx.x;

    if (tid == 0) {
        MBARRIER_INIT(sb + F2_BAR, 1);
        MBARRIER_INIT(sb + F2_BAR + 8, 1);
        MBARRIER_INIT(sb + F2_BAR + 16, 1);
    }
    __syncthreads();

    // it 0..15: GEMM2 (Wv hi+lo). it 16..31: GEMM3/4 (aa+ab). 17408B each.
    auto issueB = [&](int it) {
        int s = it & 1;
        uint32_t bar = sb + F2_BAR + 8 + s * 8;
        int np = (it >> 3) & 1, kt = it & 7;
        size_t blk = (size_t)(kt * 2 + np) * 4352;
        const __nv_bfloat16 *s0, *s1;
        if (it < 16) { s0 = g_Wvh + blk; s1 = g_Wvl + blk; }
        else         { s0 = g_aah + blk; s1 = g_abh + blk; }
        MBARRIER_EXPECT_TX(bar, 17408);
        bulk_g2s(sb + F2_B + s * 17408, s0, 8704, bar);
        bulk_g2s(sb + F2_B + s * 17408 + 8704, s1, 8704, bar);
    };

    if (tid == 0) {
        MBARRIER_EXPECT_TX(sb + F2_BAR, 81920);
        bulk_g2s(sb + F2_H, g_H + (size_t)mt * 8 * 5120, 81920, sb + F2_BAR);
        issueB(0);
        issueB(1);
    }
    float* sbias = (float*)(smem + F2_BIAS);
    float* wrow = (float*)(smem + F2_WROW);
    sbias[tid] = bv[tid];
    sbias[256 + tid] = baa[tid];
    sbias[512 + tid] = bab[tid];
    sbias[768 + tid] = acw[tid];
    if (tid < 128) wrow[tid] = 0.f;
    MBARRIER_WAIT_PARITY(sb + F2_BAR, 0);  // H tile ready
    __syncthreads();                       // biases/wrow visible

    int it = 0;
    // -------- GEMM2: F = H @ Wv + bv (hi/lo), two 128-col passes --------
    for (int np = 0; np < 2; np++) {
        float acc[4][4][4], accDummy[4][4][4];
#pragma unroll
        for (int m2 = 0; m2 < 4; m2++)
#pragma unroll
            for (int nt = 0; nt < 4; nt++)
#pragma unroll
                for (int i = 0; i < 4; i++) acc[m2][nt][i] = 0.f;
        for (int kt = 0; kt < 8; kt++, it++) {
            const int s = it & 1;
            MBARRIER_WAIT_PARITY(sb + F2_BAR + 8 + s * 8, (it >> 1) & 1);
            const char* sA = smem + F2_H + kt * 10240;
            const char* sB = smem + F2_B + s * 17408;
            mma_tile<0>(sA, sB, sB + 8704, acc, accDummy, wm, wn, lane);
            __syncthreads();
            if (tid == 0 && it + 2 < 32) issueB(it + 2);
        }
        // epilogue: F = acc + bv -> smem F image  ([chunk][128][40])
        __nv_bfloat16* Fi = (__nv_bfloat16*)(smem + F2_F);
#pragma unroll
        for (int m2 = 0; m2 < 4; m2++)
#pragma unroll
            for (int r2 = 0; r2 < 2; r2++) {
                const int rb = wm * 64 + m2 * 16 + (lane >> 2) + r2 * 8;
#pragma unroll
                for (int nt = 0; nt < 4; nt++) {
                    const int cl = wn * 32 + nt * 8 + (lane & 3) * 2;
                    const int gc = np * 128 + cl;
                    float v0 = acc[m2][nt][r2 * 2 + 0] + sbias[gc];
                    float v1 = acc[m2][nt][r2 * 2 + 1] + sbias[gc + 1];
                    *reinterpret_cast<__nv_bfloat162*>(
                        Fi + (gc >> 5) * 5120 + rb * 40 + (gc & 31)) =
                        __floats2bfloat162_rn(v0, v1);
                }
            }
    }
    __syncthreads();  // F image complete

    // -------- GEMM3/4: U = F@aa, G = F@ab (dual acc), + gated score --------
    for (int np = 0; np < 2; np++) {
        float aU[4][4][4], aG[4][4][4];
#pragma unroll
        for (int m2 = 0; m2 < 4; m2++)
#pragma unroll
            for (int nt = 0; nt < 4; nt++)
#pragma unroll
                for (int i = 0; i < 4; i++) { aU[m2][nt][i] = 0.f; aG[m2][nt][i] = 0.f; }
        for (int kt = 0; kt < 8; kt++, it++) {
            const int s = it & 1;
            MBARRIER_WAIT_PARITY(sb + F2_BAR + 8 + s * 8, (it >> 1) & 1);
            const char* sA = smem + F2_F + kt * 10240;
            const char* sB = smem + F2_B + s * 17408;
            mma_tile<1>(sA, sB, sB + 8704, aU, aG, wm, wn, lane);
            __syncthreads();
            if (tid == 0 && it + 2 < 32) issueB(it + 2);
        }
        // partial gated score per owned cell, reduce across quad, atomics to wrow
#pragma unroll
        for (int m2 = 0; m2 < 4; m2++)
#pragma unroll
            for (int r2 = 0; r2 < 2; r2++) {
                const int rb = wm * 64 + m2 * 16 + (lane >> 2) + r2 * 8;
                float rs = 0.f;
#pragma unroll
                for (int nt = 0; nt < 4; nt++)
#pragma unroll
                    for (int c2 = 0; c2 < 2; c2++) {
                        const int gc = np * 128 + wn * 32 + nt * 8 + (lane & 3) * 2 + c2;
                        float u = tanhf(aU[m2][nt][r2 * 2 + c2] + sbias[256 + gc]);
                        float g = 1.f / (1.f + expf(-(aG[m2][nt][r2 * 2 + c2] + sbias[512 + gc])));
                        rs += g * u * sbias[768 + gc];
                    }
                rs += __shfl_xor_sync(0xffffffffu, rs, 1);
                rs += __shfl_xor_sync(0xffffffffu, rs, 2);
                if ((lane & 3) == 0) atomicAdd(&wrow[rb], rs);
            }
    }
    __syncthreads();

    // exp weights (|score| tiny -> no max subtraction), mask padded rows
    if (tid < 128) {
        const int gr = mt * 128 + tid;
        wrow[tid] = (gr < M) ? expf(wrow[tid]) : 0.f;
    }
    __syncthreads();

    // pooling: P[c] += sum_r w_r * F[r,c];  P[256] += sum_r w_r
    {
        const int c = tid;
        const __nv_bfloat16* col =
            (const __nv_bfloat16*)(smem + F2_F) + (c >> 5) * 5120 + (c & 31);
        float a = 0.f;
#pragma unroll 4
        for (int r = 0; r < 128; r++) a += wrow[r] * __bfloat162float(col[r * 40]);
        atomicAdd(&g_P[c], a);
    }
    if (wid == 0) {
        float s = wrow[lane] + wrow[lane + 32] + wrow[lane + 64] + wrow[lane + 96];
#pragma unroll
        for (int o = 16; o; o >>= 1) s += __shfl_xor_sync(0xffffffffu, s, o);
        if (lane == 0) atomicAdd(&g_P[256], s);
    }
}

// ---------------- classifier ----------------
__global__ void cls_k(const float* __restrict__ P, const float* __restrict__ c1w,
                      const float* __restrict__ c1b, const float* __restrict__ c2w,
                      const float* __restrict__ c2b, float* __restrict__ out) {
    __shared__ float pd[256], h[128];
    int t = threadIdx.x;  // 128 threads
    float denom = P[256];
    pd[t] = P[t] / denom;
    pd[t + 128] = P[t + 128] / denom;
    __syncthreads();
    float s = c1b[t];
#pragma unroll 8
    for (int d = 0; d < 256; d++) s += pd[d] * c1w[d * 128 + t];
    h[t] = fmaxf(s, 0.f);
    __syncthreads();
    if (t < 4) {
        float o = c2b[t];
#pragma unroll 8
        for (int j = 0; j < 128; j++) o += h[j] * c2w[j * 4 + t];
        out[t] = o;
    }
}

extern "C" void kernel_launch(void* const* d_in, const int* in_sizes, int n_in,
                              void* d_out, int out_size) {
    const float* x_path = (const float*)d_in[0];
    const float* wsi_w = (const float*)d_in[2];
    const float* wsi_b = (const float*)d_in[3];
    const float* wv_w = (const float*)d_in[10];
    const float* wv_b = (const float*)d_in[11];
    const float* aa_w = (const float*)d_in[12];
    const float* aa_b = (const float*)d_in[13];
    const float* ab_w = (const float*)d_in[14];
    const float* ab_b = (const float*)d_in[15];
    const float* ac_w = (const float*)d_in[16];
    const float* c1_w = (const float*)d_in[18];
    const float* c1_b = (const float*)d_in[19];
    const float* c2_w = (const float*)d_in[20];
    const float* c2_b = (const float*)d_in[21];

    const int M = in_sizes[0] / 1024;
    const int NT = (M + 127) / 128;

    cudaFuncSetAttribute(gemm1_k, cudaFuncAttributeMaxDynamicSharedMemorySize,
                         G1_SMEM);
    cudaFuncSetAttribute(fused2_k, cudaFuncAttributeMaxDynamicSharedMemorySize,
                         F2_SMEM);

    void* p;
    float* P;
    cudaGetSymbolAddress(&p, g_P); P = (float*)p;

    prep_all<<<1793, 256>>>(wsi_w, wv_w, aa_w, ab_w);
    gemm1_k<<<dim3(2, NT), 256, G1_SMEM>>>(x_path, wsi_b, M);
    fused2_k<<<NT, 256, F2_SMEM>>>(wv_b, aa_b, ab_b, ac_w, M);
    cls_k<<<1, 128>>>(P, c1_w, c1_b, c2_w, c2_b, (float*)d_out);
}

// round 17
// speedup vs baseline: 2.5651x; 1.0364x over previous
#include <cuda_runtime.h>
#include <cuda_bf16.h>
#include <cstdint>

// ============================================================================
// MCAT fused pipeline, mma.sync + cp.async.bulk edition (tcgen05 unavailable:
// harness compiles via compute_103 PTX; tcgen05 is sm_103a-only).
//
// Math: softmax over size-1 axis == 1 => fused = h_path@wv + bv; q/k/x_cell
// dead. ac_b softmax-invariant => dropped.
// Precision: W1 single bf16 (error decorrelates through relu+3 GEMMs+nonlin
// before pooling). Wv hi/lo: pooled output is linear in F, so dWv is
// systematic (R12 lesson). aa/ab single bf16 (perturb attention weights only).
// R14 lesson: g_P[256] (pool denominator) MUST be zeroed every call — device
// globals are only zero-initialized at module load, and graph replays
// accumulate otherwise.
//
//   prep_all: all weights -> bf16 padded smem-image blocks [32][136]; zero P.
//   gemm1: H = relu(X@W1+b1). A: f32 LDG->cvt->STS double buffer,
//          B: 2-stage cp.async.bulk+mbarrier. Grid (2,NT): X tile L2 reuse.
//   fused2 (1 CTA / 128 rows): bulk-load H tile; F = H@Wv+bv (hi/lo) -> smem;
//          U = F@aa, G = F@ab (dual acc); score = sum sigmoid*tanh*ac;
//          pooled sums via atomics. F/U/G never touch HBM.
//   cls: classifier MLP, 1024 threads (R16 ncu: 128-thread version was 27us
//        DRAM-latency-bound on the 131KB c1_w read; 8-way d-split lifts MLP).
// Warp layout 2m x 4n (64 rows x 32 cols per warp): halves redundant
// B-ldmatrix traffic vs 4m x 2n for dual/hi-lo tiles.
// ============================================================================

#define MAXT 391

__device__ __align__(1024) __nv_bfloat16 g_W1h[64 * 4352];  // [kt*2+nh][32][136]
__device__ __align__(1024) __nv_bfloat16 g_Wvh[16 * 4352];
__device__ __align__(1024) __nv_bfloat16 g_Wvl[16 * 4352];
__device__ __align__(1024) __nv_bfloat16 g_aah[16 * 4352];
__device__ __align__(1024) __nv_bfloat16 g_abh[16 * 4352];
__device__ __align__(1024) __nv_bfloat16 g_H[(size_t)MAXT * 8 * 5120]; // [mt][chunk][128][40]
__device__ float g_P[272];

// ---------------- PTX helpers ----------------
__device__ __forceinline__ uint32_t s2u(const void* p) {
    return (uint32_t)__cvta_generic_to_shared(p);
}
#define MBARRIER_INIT(mb, cnt) \
    asm volatile("mbarrier.init.shared.b64 [%0], %1;" :: "r"((uint32_t)(mb)), \
                 "r"((uint32_t)(cnt)) : "memory")
#define MBARRIER_EXPECT_TX(mb, tx) \
    asm volatile("mbarrier.arrive.expect_tx.shared.b64 _, [%0], %1;" \
                 :: "r"((uint32_t)(mb)), "r"((uint32_t)(tx)) : "memory")
#define MBARRIER_WAIT_PARITY(mb, par) do {                                     \
    uint32_t _mb = (uint32_t)(mb), _p = (uint32_t)(par), _done;                \
    asm volatile("{\n\t.reg .pred p;\n\t"                                      \
        "mbarrier.try_wait.parity.acquire.cta.shared::cta.b64 p, [%1], %2;\n\t"\
        "selp.b32 %0, 1, 0, p;\n\t}" : "=r"(_done) : "r"(_mb), "r"(_p) : "memory"); \
    if (!_done) {                                                              \
        asm volatile("{\n\t.reg .pred P1;\n\t"                                 \
            "WL_%=:\n\t"                                                       \
            "mbarrier.try_wait.parity.acquire.cta.shared::cta.b64 P1, [%0], %1, 0x989680;\n\t" \
            "@P1 bra.uni WD_%=;\n\t"                                           \
            "bra.uni WL_%=;\n\t"                                               \
            "WD_%=:\n\t}" :: "r"(_mb), "r"(_p) : "memory");                    \
    }                                                                          \
} while (0)

__device__ __forceinline__ void bulk_g2s(uint32_t dst, const void* src,
                                         uint32_t bytes, uint32_t mbar) {
    asm volatile(
        "cp.async.bulk.shared::cta.global.mbarrier::complete_tx::bytes "
        "[%0], [%1], %2, [%3];"
        :: "r"(dst), "l"(src), "r"(bytes), "r"(mbar) : "memory");
}
__device__ __forceinline__ void ldsm_x4(uint32_t (&r)[4], const void* p) {
    uint32_t a = s2u(p);
    asm volatile("ldmatrix.sync.aligned.m8n8.x4.shared.b16 {%0,%1,%2,%3}, [%4];"
                 : "=r"(r[0]), "=r"(r[1]), "=r"(r[2]), "=r"(r[3]) : "r"(a));
}
__device__ __forceinline__ void ldsm_x2t(uint32_t (&r)[2], const void* p) {
    uint32_t a = s2u(p);
    asm volatile("ldmatrix.sync.aligned.m8n8.x2.trans.shared.b16 {%0,%1}, [%2];"
                 : "=r"(r[0]), "=r"(r[1]) : "r"(a));
}
__device__ __forceinline__ void mma_bf16(float (&c)[4], const uint32_t (&a)[4],
                                         const uint32_t (&b)[2]) {
    asm volatile(
        "mma.sync.aligned.m16n8k16.row.col.f32.bf16.bf16.f32 "
        "{%0,%1,%2,%3}, {%4,%5,%6,%7}, {%8,%9}, {%0,%1,%2,%3};"
        : "+f"(c[0]), "+f"(c[1]), "+f"(c[2]), "+f"(c[3])
        : "r"(a[0]), "r"(a[1]), "r"(a[2]), "r"(a[3]), "r"(b[0]), "r"(b[1]));
}

// One 128x256(x32k) MMA step from padded smem images, 2m x 4n warp layout.
// sA: [128][40] bf16 (80B rows). sB0/sB1: [32][136] bf16 (272B rows).
// wm = wid&1 (rows wm*64..+63 as 4 m16 tiles), wn = wid>>1 (cols wn*32..+31
// as 4 n8 tiles).
// MODE 0: sB0 and sB1 both accumulate into accA (hi/lo sum).
// MODE 1: sB0 -> accA, sB1 -> accB (dual outputs).
// MODE 2: sB0 -> accA only (sB1 unused).
template <int MODE>
__device__ __forceinline__ void mma_tile(const char* sA, const char* sB0,
                                         const char* sB1, float (&accA)[4][4][4],
                                         float (&accB)[4][4][4], int wm, int wn,
                                         int lane) {
#pragma unroll
    for (int ks = 0; ks < 2; ks++) {
        uint32_t af[4][4];
#pragma unroll
        for (int m2 = 0; m2 < 4; m2++)
            ldsm_x4(af[m2], sA + (wm * 64 + m2 * 16 + (lane & 15)) * 80 +
                                (ks * 16 + (lane >> 4) * 8) * 2);
#pragma unroll
        for (int nt = 0; nt < 4; nt++) {
            uint32_t b0[2], b1[2];
            const int br = ks * 16 + (lane & 15);
            const int bc = wn * 32 + nt * 8;
            ldsm_x2t(b0, sB0 + br * 272 + bc * 2);
            if (MODE != 2) ldsm_x2t(b1, sB1 + br * 272 + bc * 2);
#pragma unroll
            for (int m2 = 0; m2 < 4; m2++) {
                mma_bf16(accA[m2][nt], af[m2], b0);
                if (MODE == 0)      mma_bf16(accA[m2][nt], af[m2], b1);
                else if (MODE == 1) mma_bf16(accB[m2][nt], af[m2], b1);
            }
        }
    }
}

// ---------------- prep: all weights -> padded bf16 images; zero P -----------
__device__ __forceinline__ void prep_one(const float* W, __nv_bfloat16* Dh,
                                         __nv_bfloat16* Dl, int i) {
    int k = i >> 8, n = i & 255;
    int kt = k >> 5, ik = k & 31, nh = n >> 7, j = n & 127;
    size_t off = (size_t)(kt * 2 + nh) * 4352 + ik * 136 + j;
    float v = W[i];
    __nv_bfloat16 h = __float2bfloat16(v);
    Dh[off] = h;
    if (Dl) Dl[off] = __float2bfloat16(v - __bfloat162float(h));
}

__global__ void prep_all(const float* __restrict__ w1, const float* __restrict__ wv,
                         const float* __restrict__ aa, const float* __restrict__ ab) {
    int b = blockIdx.x, tid = threadIdx.x;
    if (b < 1024) {
        prep_one(w1, g_W1h, nullptr, b * 256 + tid);
    } else if (b < 1280) {
        prep_one(wv, g_Wvh, g_Wvl, (b - 1024) * 256 + tid);
    } else if (b < 1536) {
        prep_one(aa, g_aah, nullptr, (b - 1280) * 256 + tid);
    } else if (b < 1792) {
        prep_one(ab, g_abh, nullptr, (b - 1536) * 256 + tid);
    } else {
        // zero ALL 272 floats incl. g_P[256] denominator (R14 lesson:
        // blockDim is 256, so tid<272 alone misses 256..271).
        g_P[tid] = 0.f;
        if (tid < 16) g_P[256 + tid] = 0.f;
    }
}

// ---------------- GEMM1: H = relu(X @ W1 + b1), single-bf16 W1 ----------------
#define G1_A    0          // 2 x 10240  (A bufs, [128][40] bf16)
#define G1_B    20480      // 2 x 8704   (B stages, hi only)
#define G1_BAR  37888      // 2 mbarriers
#define G1_SMEM 38016

__global__ __launch_bounds__(256, 2) void gemm1_k(
    const float* __restrict__ X, const float* __restrict__ b1, int M) {
    extern __shared__ __align__(128) char smem[];
    uint32_t sb = s2u(smem);
    const int tid = threadIdx.x, lane = tid & 31, wid = tid >> 5;
    const int wm = wid & 1, wn = wid >> 1;
    const int nh = blockIdx.x, mt = blockIdx.y;   // nh fastest: X tile L2 reuse
    const int mBase = mt * 128;

    if (tid == 0) {
        MBARRIER_INIT(sb + G1_BAR, 1);
        MBARRIER_INIT(sb + G1_BAR + 8, 1);
    }

    // A staging: thread covers row r = tid>>1, 16 cols at (tid&1)*16
    const int ar = tid >> 1, ac = (tid & 1) * 16;
    float4 st[4];
    auto loadA = [&](int kt) {
        const int gr = mBase + ar;
        if (gr < M) {
            const float* src = X + (size_t)gr * 1024 + kt * 32 + ac;
#pragma unroll
            for (int i = 0; i < 4; i++)
                st[i] = *reinterpret_cast<const float4*>(src + i * 4);
        } else {
#pragma unroll
            for (int i = 0; i < 4; i++) st[i] = make_float4(0.f, 0.f, 0.f, 0.f);
        }
    };
    auto storeA = [&](int kt) {
        char* dst = smem + G1_A + (kt & 1) * 10240 + ar * 80 + ac * 2;
#pragma unroll
        for (int i = 0; i < 4; i++) {
            __nv_bfloat162* p = reinterpret_cast<__nv_bfloat162*>(dst + i * 8);
            p[0] = __floats2bfloat162_rn(st[i].x, st[i].y);
            p[1] = __floats2bfloat162_rn(st[i].z, st[i].w);
        }
    };
    auto issueB = [&](int kt) {
        int s = kt & 1;
        uint32_t bar = sb + G1_BAR + s * 8;
        MBARRIER_EXPECT_TX(bar, 8704);
        bulk_g2s(sb + G1_B + s * 8704, g_W1h + (size_t)(kt * 2 + nh) * 4352,
                 8704, bar);
    };

    __syncthreads();  // barriers initialized before any expect_tx
    loadA(0);
    if (tid == 0) { issueB(0); issueB(1); }
    storeA(0);
    loadA(1);
    __syncthreads();  // A buf0 visible

    float acc[4][4][4];
    float accDummy[4][4][4];
#pragma unroll
    for (int m2 = 0; m2 < 4; m2++)
#pragma unroll
        for (int nt = 0; nt < 4; nt++)
#pragma unroll
            for (int i = 0; i < 4; i++) acc[m2][nt][i] = 0.f;

    for (int kt = 0; kt < 32; kt++) {
        const int s = kt & 1;
        MBARRIER_WAIT_PARITY(sb + G1_BAR + s * 8, (kt >> 1) & 1);
        const char* sA = smem + G1_A + s * 10240;
        const char* sB = smem + G1_B + s * 8704;
        mma_tile<2>(sA, sB, nullptr, acc, accDummy, wm, wn, lane);
        if (kt + 1 < 32) storeA(kt + 1);
        __syncthreads();  // A(kt+1) visible; B stage s drained by all warps
        if (kt + 2 < 32) {
            if (tid == 0) issueB(kt + 2);
            loadA(kt + 2);
        }
    }

    // epilogue: relu(acc + b1) -> g_H padded tile layout [mt][chunk][128][40]
    __nv_bfloat16* Ht = g_H + (size_t)mt * 8 * 5120;
#pragma unroll
    for (int m2 = 0; m2 < 4; m2++) {
#pragma unroll
        for (int r2 = 0; r2 < 2; r2++) {
            const int rb = wm * 64 + m2 * 16 + (lane >> 2) + r2 * 8;
#pragma unroll
            for (int nt = 0; nt < 4; nt++) {
                const int cl = wn * 32 + nt * 8 + (lane & 3) * 2;
                const int gc = nh * 128 + cl;
                float v0 = fmaxf(acc[m2][nt][r2 * 2 + 0] + b1[gc], 0.f);
                float v1 = fmaxf(acc[m2][nt][r2 * 2 + 1] + b1[gc + 1], 0.f);
                *reinterpret_cast<__nv_bfloat162*>(
                    Ht + (gc >> 5) * 5120 + rb * 40 + (gc & 31)) =
                    __floats2bfloat162_rn(v0, v1);
            }
        }
    }
}

// ---------------- fused2: F, U, G, score, pooling ----------------
#define F2_H    0           // 81920: H tile image (8 chunks x [128][40])
#define F2_F    81920       // 81920: F image, same layout
#define F2_B    163840      // 2 stages x 17408
#define F2_BIAS 198656      // 1024 f32: bv, baa, bab, ac
#define F2_WROW 202752      // 128 f32
#define F2_BAR  203264      // barH + 2 stage bars
#define F2_SMEM 203392

__global__ __launch_bounds__(256, 1) void fused2_k(
    const float* __restrict__ bv, const float* __restrict__ baa,
    const float* __restrict__ bab, const float* __restrict__ acw, int M) {
    extern __shared__ __align__(128) char smem[];
    uint32_t sb = s2u(smem);
    const int tid = threadIdx.x, lane = tid & 31, wid = tid >> 5;
    const int wm = wid & 1, wn = wid >> 1;
    const int mt = blockIdx.x;

    if (tid == 0) {
        MBARRIER_INIT(sb + F2_BAR, 1);
        MBARRIER_INIT(sb + F2_BAR + 8, 1);
        MBARRIER_INIT(sb + F2_BAR + 16, 1);
    }
    __syncthreads();

    // it 0..15: GEMM2 (Wv hi+lo). it 16..31: GEMM3/4 (aa+ab). 17408B each.
    auto issueB = [&](int it) {
        int s = it & 1;
        uint32_t bar = sb + F2_BAR + 8 + s * 8;
        int np = (it >> 3) & 1, kt = it & 7;
        size_t blk = (size_t)(kt * 2 + np) * 4352;
        const __nv_bfloat16 *s0, *s1;
        if (it < 16) { s0 = g_Wvh + blk; s1 = g_Wvl + blk; }
        else         { s0 = g_aah + blk; s1 = g_abh + blk; }
        MBARRIER_EXPECT_TX(bar, 17408);
        bulk_g2s(sb + F2_B + s * 17408, s0, 8704, bar);
        bulk_g2s(sb + F2_B + s * 17408 + 8704, s1, 8704, bar);
    };

    if (tid == 0) {
        MBARRIER_EXPECT_TX(sb + F2_BAR, 81920);
        bulk_g2s(sb + F2_H, g_H + (size_t)mt * 8 * 5120, 81920, sb + F2_BAR);
        issueB(0);
        issueB(1);
    }
    float* sbias = (float*)(smem + F2_BIAS);
    float* wrow = (float*)(smem + F2_WROW);
    sbias[tid] = bv[tid];
    sbias[256 + tid] = baa[tid];
    sbias[512 + tid] = bab[tid];
    sbias[768 + tid] = acw[tid];
    if (tid < 128) wrow[tid] = 0.f;
    MBARRIER_WAIT_PARITY(sb + F2_BAR, 0);  // H tile ready
    __syncthreads();                       // biases/wrow visible

    int it = 0;
    // -------- GEMM2: F = H @ Wv + bv (hi/lo), two 128-col passes --------
    for (int np = 0; np < 2; np++) {
        float acc[4][4][4], accDummy[4][4][4];
#pragma unroll
        for (int m2 = 0; m2 < 4; m2++)
#pragma unroll
            for (int nt = 0; nt < 4; nt++)
#pragma unroll
                for (int i = 0; i < 4; i++) acc[m2][nt][i] = 0.f;
        for (int kt = 0; kt < 8; kt++, it++) {
            const int s = it & 1;
            MBARRIER_WAIT_PARITY(sb + F2_BAR + 8 + s * 8, (it >> 1) & 1);
            const char* sA = smem + F2_H + kt * 10240;
            const char* sB = smem + F2_B + s * 17408;
            mma_tile<0>(sA, sB, sB + 8704, acc, accDummy, wm, wn, lane);
            __syncthreads();
            if (tid == 0 && it + 2 < 32) issueB(it + 2);
        }
        // epilogue: F = acc + bv -> smem F image  ([chunk][128][40])
        __nv_bfloat16* Fi = (__nv_bfloat16*)(smem + F2_F);
#pragma unroll
        for (int m2 = 0; m2 < 4; m2++)
#pragma unroll
            for (int r2 = 0; r2 < 2; r2++) {
                const int rb = wm * 64 + m2 * 16 + (lane >> 2) + r2 * 8;
#pragma unroll
                for (int nt = 0; nt < 4; nt++) {
                    const int cl = wn * 32 + nt * 8 + (lane & 3) * 2;
                    const int gc = np * 128 + cl;
                    float v0 = acc[m2][nt][r2 * 2 + 0] + sbias[gc];
                    float v1 = acc[m2][nt][r2 * 2 + 1] + sbias[gc + 1];
                    *reinterpret_cast<__nv_bfloat162*>(
                        Fi + (gc >> 5) * 5120 + rb * 40 + (gc & 31)) =
                        __floats2bfloat162_rn(v0, v1);
                }
            }
    }
    __syncthreads();  // F image complete

    // -------- GEMM3/4: U = F@aa, G = F@ab (dual acc), + gated score --------
    for (int np = 0; np < 2; np++) {
        float aU[4][4][4], aG[4][4][4];
#pragma unroll
        for (int m2 = 0; m2 < 4; m2++)
#pragma unroll
            for (int nt = 0; nt < 4; nt++)
#pragma unroll
                for (int i = 0; i < 4; i++) { aU[m2][nt][i] = 0.f; aG[m2][nt][i] = 0.f; }
        for (int kt = 0; kt < 8; kt++, it++) {
            const int s = it & 1;
            MBARRIER_WAIT_PARITY(sb + F2_BAR + 8 + s * 8, (it >> 1) & 1);
            const char* sA = smem + F2_F + kt * 10240;
            const char* sB = smem + F2_B + s * 17408;
            mma_tile<1>(sA, sB, sB + 8704, aU, aG, wm, wn, lane);
            __syncthreads();
            if (tid == 0 && it + 2 < 32) issueB(it + 2);
        }
        // partial gated score per owned cell, reduce across quad, atomics to wrow
#pragma unroll
        for (int m2 = 0; m2 < 4; m2++)
#pragma unroll
            for (int r2 = 0; r2 < 2; r2++) {
                const int rb = wm * 64 + m2 * 16 + (lane >> 2) + r2 * 8;
                float rs = 0.f;
#pragma unroll
                for (int nt = 0; nt < 4; nt++)
#pragma unroll
                    for (int c2 = 0; c2 < 2; c2++) {
                        const int gc = np * 128 + wn * 32 + nt * 8 + (lane & 3) * 2 + c2;
                        float u = tanhf(aU[m2][nt][r2 * 2 + c2] + sbias[256 + gc]);
                        float g = 1.f / (1.f + expf(-(aG[m2][nt][r2 * 2 + c2] + sbias[512 + gc])));
                        rs += g * u * sbias[768 + gc];
                    }
                rs += __shfl_xor_sync(0xffffffffu, rs, 1);
                rs += __shfl_xor_sync(0xffffffffu, rs, 2);
                if ((lane & 3) == 0) atomicAdd(&wrow[rb], rs);
            }
    }
    __syncthreads();

    // exp weights (|score| tiny -> no max subtraction), mask padded rows
    if (tid < 128) {
        const int gr = mt * 128 + tid;
        wrow[tid] = (gr < M) ? expf(wrow[tid]) : 0.f;
    }
    __syncthreads();

    // pooling: P[c] += sum_r w_r * F[r,c];  P[256] += sum_r w_r
    {
        const int c = tid;
        const __nv_bfloat16* col =
            (const __nv_bfloat16*)(smem + F2_F) + (c >> 5) * 5120 + (c & 31);
        float a = 0.f;
#pragma unroll 4
        for (int r = 0; r < 128; r++) a += wrow[r] * __bfloat162float(col[r * 40]);
        atomicAdd(&g_P[c], a);
    }
    if (wid == 0) {
        float s = wrow[lane] + wrow[lane + 32] + wrow[lane + 64] + wrow[lane + 96];
#pragma unroll
        for (int o = 16; o; o >>= 1) s += __shfl_xor_sync(0xffffffffu, s, o);
        if (lane == 0) atomicAdd(&g_P[256], s);
    }
}

// ---------------- classifier: 1024 threads, 8-way d-split ----------------
__global__ __launch_bounds__(1024) void cls_k(
    const float* __restrict__ P, const float* __restrict__ c1w,
    const float* __restrict__ c1b, const float* __restrict__ c2w,
    const float* __restrict__ c2b, float* __restrict__ out) {
    __shared__ float pd[256], part[8][128], h[128], out4[4];
    const int t = threadIdx.x;  // 0..1023
    if (t < 256) pd[t] = P[t] / P[256];
    if (t < 4) out4[t] = 0.f;
    __syncthreads();
    // layer 1: h = relu(pd @ c1w + c1b); 8 d-groups x 128 outputs
    const int g = t >> 7, tt = t & 127;
    float s = 0.f;
#pragma unroll 8
    for (int d = g * 32; d < g * 32 + 32; d++) s += pd[d] * c1w[d * 128 + tt];
    part[g][tt] = s;
    __syncthreads();
    if (t < 128) {
        float v = c1b[t];
#pragma unroll
        for (int q = 0; q < 8; q++) v += part[q][t];
        h[t] = fmaxf(v, 0.f);
    }
    __syncthreads();
    // layer 2: out = h @ c2w + c2b (128 threads, float4 row each, smem atomics)
    if (t < 128) {
        float hv = h[t];
        float4 w = reinterpret_cast<const float4*>(c2w)[t];
        atomicAdd(&out4[0], hv * w.x);
        atomicAdd(&out4[1], hv * w.y);
        atomicAdd(&out4[2], hv * w.z);
        atomicAdd(&out4[3], hv * w.w);
    }
    __syncthreads();
    if (t < 4) out[t] = out4[t] + c2b[t];
}

extern "C" void kernel_launch(void* const* d_in, const int* in_sizes, int n_in,
                              void* d_out, int out_size) {
    const float* x_path = (const float*)d_in[0];
    const float* wsi_w = (const float*)d_in[2];
    const float* wsi_b = (const float*)d_in[3];
    const float* wv_w = (const float*)d_in[10];
    const float* wv_b = (const float*)d_in[11];
    const float* aa_w = (const float*)d_in[12];
    const float* aa_b = (const float*)d_in[13];
    const float* ab_w = (const float*)d_in[14];
    const float* ab_b = (const float*)d_in[15];
    const float* ac_w = (const float*)d_in[16];
    const float* c1_w = (const float*)d_in[18];
    const float* c1_b = (const float*)d_in[19];
    const float* c2_w = (const float*)d_in[20];
    const float* c2_b = (const float*)d_in[21];

    const int M = in_sizes[0] / 1024;
    const int NT = (M + 127) / 128;

    cudaFuncSetAttribute(gemm1_k, cudaFuncAttributeMaxDynamicSharedMemorySize,
                         G1_SMEM);
    cudaFuncSetAttribute(fused2_k, cudaFuncAttributeMaxDynamicSharedMemorySize,
                         F2_SMEM);

    void* p;
    float* P;
    cudaGetSymbolAddress(&p, g_P); P = (float*)p;

    prep_all<<<1793, 256>>>(wsi_w, wv_w, aa_w, ab_w);
    gemm1_k<<<dim3(2, NT), 256, G1_SMEM>>>(x_path, wsi_b, M);
    fused2_k<<<NT, 256, F2_SMEM>>>(wv_b, aa_b, ab_b, ac_w, M);
    cls_k<<<1, 1024>>>(P, c1_w, c1_b, c2_w, c2_b, (float*)d_out);
}